// round 11
// baseline (speedup 1.0000x reference)
#include <cuda_runtime.h>
#include <cuda_fp16.h>
#include <mma.h>
#include <math.h>

using namespace nvcuda;

typedef unsigned long long ull;

#define N_NODES 50000
#define N_PAD   50048
#define N_EDGES 800000
#define D 128
#define D_RED 32
#define EG 782          // ceil(200000/256) int4 edge blocks
#define EG8 391         // ceil(100000/256) 8-edge blocks
#define DOTG 98         // ceil(50000/512) dot blocks
#define HOPG 3125       // ceil(50000/16) hop blocks
#define LDMA 136        // skewed smem leading dim (halves)

// ---------------- scratch ----------------
__device__ __half g_w16[3][D * D];
__device__ __half g_h[3][N_PAD * D];
__device__ __half g_bufA[N_NODES * D];
__device__ __half g_bufB[N_NODES * D];
__device__ int    g_counts[N_NODES];
__device__ int    g_rowptr[N_NODES + 1];
__device__ int    g_cursor[N_NODES];
__device__ int    g_perm[N_NODES];
__device__ uint2  g_epack[N_EDGES];
__device__ float  g_r1[N_NODES];
__device__ float  g_r2[N_NODES];
__device__ float  g_dot[3 * D];
__device__ float  g_attn[3 * D];
__device__ float  g_cb[D];
__device__ int    g_done;

__device__ __forceinline__ float fast_tanh(float x) {
    float t = __expf(2.0f * x);
    return 1.0f - __fdividef(2.0f, t + 1.0f);
}

// ================= K1: zero + W->fp16 =================
__global__ __launch_bounds__(256) void k1_kernel(const float* __restrict__ W1,
                                                 const float* __restrict__ W2,
                                                 const float* __restrict__ W3) {
    int bx = blockIdx.x, tid = threadIdx.x;
    if (bx < 196) {
        int i = bx * 256 + tid;
        if (i < N_NODES) {
            g_counts[i] = 0;
            g_r1[i] = 0.f; g_r2[i] = 0.f;
        }
        if (i < 3 * D) g_dot[i] = 0.f;
    } else {
        int idx = (bx - 196) * 256 + tid;   // 48 blocks -> 12288 float4s
        int k = idx / 4096, o4 = idx % 4096;
        const float4* Wk4 = (const float4*)(k == 0 ? W1 : k == 1 ? W2 : W3);
        float4 w = Wk4[o4];
        __half2 h0 = __floats2half2_rn(w.x, w.y);
        __half2 h1 = __floats2half2_rn(w.z, w.w);
        ((uint2*)g_w16[k])[o4] = make_uint2(*(unsigned*)&h0, *(unsigned*)&h1);
    }
}

// ================= gemm body (fp32 X staged+converted, skewed smem) ==========
__device__ __forceinline__ void gemm_body(int k, int rb, const float* __restrict__ X) {
    __shared__ __half As[64 * LDMA];   // 17408 B
    __shared__ __half Bs[64 * LDMA];   // 17408 B
    int tid = threadIdx.x;
    int row0 = rb * 64;
    __half* out = g_h[k];

    // Stage A: read fp32 X, convert to fp16 into skewed layout.
    {
        const float4* X4 = (const float4*)X;
        for (int i = tid; i < 64 * 32; i += 256) {
            int r = i >> 5, c4 = i & 31;
            int rc = min(row0 + r, N_NODES - 1);
            float4 f = X4[rc * 32 + c4];
            __half2 h0 = __floats2half2_rn(f.x, f.y);
            __half2 h1 = __floats2half2_rn(f.z, f.w);
            *(uint2*)(As + r * LDMA + c4 * 4) =
                make_uint2(*(unsigned*)&h0, *(unsigned*)&h1);
        }
    }

    int warp = tid >> 5;
    int wr = warp >> 1;
    int wc0 = (warp & 1) * 4;

    wmma::fragment<wmma::accumulator, 16, 16, 16, float> acc[4];
#pragma unroll
    for (int c = 0; c < 4; ++c) wmma::fill_fragment(acc[c], 0.f);

#pragma unroll
    for (int ph = 0; ph < 2; ++ph) {
        __syncthreads();
        {
            const uint4* wsrc = (const uint4*)(g_w16[k] + ph * 64 * D);
            for (int i = tid; i < 64 * 16; i += 256) {
                int r = i >> 4, c4 = i & 15;
                *(uint4*)(Bs + r * LDMA + c4 * 8) = wsrc[i];
            }
        }
        __syncthreads();
#pragma unroll
        for (int k16 = 0; k16 < 4; ++k16) {
            wmma::fragment<wmma::matrix_a, 16, 16, 16, __half, wmma::row_major> a;
            wmma::load_matrix_sync(a, As + wr * 16 * LDMA + (ph * 4 + k16) * 16, LDMA);
#pragma unroll
            for (int c = 0; c < 4; ++c) {
                wmma::fragment<wmma::matrix_b, 16, 16, 16, __half, wmma::row_major> b;
                wmma::load_matrix_sync(b, Bs + k16 * 16 * LDMA + (wc0 + c) * 16, LDMA);
                wmma::mma_sync(acc[c], a, b, acc[c]);
            }
        }
    }
#pragma unroll
    for (int c = 0; c < 4; ++c) {
        wmma::fragment<wmma::accumulator, 16, 16, 16, __half> hacc;
#pragma unroll
        for (int i = 0; i < hacc.num_elements; ++i)
            hacc.x[i] = __float2half(fast_tanh(acc[c].x[i]));
        wmma::store_matrix_sync(out + (row0 + wr * 16) * D + (wc0 + c) * 16, hacc, D,
                                wmma::mem_row_major);
    }
}

// ================= K2: count_r1 || gemm, interleaved 1:3 =================
// grid = 782*4 = 3128
__global__ __launch_bounds__(256) void k2_kernel(const float* __restrict__ X,
                                                 const int* __restrict__ erow,
                                                 const int* __restrict__ ecol,
                                                 const float* __restrict__ eval_) {
    int grp = blockIdx.x >> 2, sl = blockIdx.x & 3;
    if (sl == 0) {
        int i = grp * 256 + threadIdx.x;
        if (i < N_EDGES / 4) {
            int4 r = ((const int4*)erow)[i];
            int4 c = ((const int4*)ecol)[i];
            float4 v = ((const float4*)eval_)[i];
            atomicAdd(&g_counts[r.x], 1);
            atomicAdd(&g_counts[r.y], 1);
            atomicAdd(&g_counts[r.z], 1);
            atomicAdd(&g_counts[r.w], 1);
            atomicAdd(&g_r1[c.x], v.x);
            atomicAdd(&g_r1[c.y], v.y);
            atomicAdd(&g_r1[c.z], v.z);
            atomicAdd(&g_r1[c.w], v.w);
        }
    } else {
        int gi = grp * 3 + (sl - 1);      // 0..2345
        gemm_body(gi / 782, gi % 782, X);
    }
}

// ================= K3: scan + degree counting-sort =================
__global__ void scan_kernel() {
    const int PER = 49;
    int t = threadIdx.x;
    int base = t * PER;
    int sum = 0;
    for (int i = 0; i < PER; ++i) {
        int idx = base + i;
        if (idx < N_NODES) sum += g_counts[idx];
    }
    int lane = t & 31, wid = t >> 5;
    int x = sum;
#pragma unroll
    for (int o = 1; o < 32; o <<= 1) {
        int y = __shfl_up_sync(0xffffffffu, x, o);
        if (lane >= o) x += y;
    }
    __shared__ int wsum[32];
    if (lane == 31) wsum[wid] = x;
    __syncthreads();
    if (wid == 0) {
        int w = wsum[lane];
#pragma unroll
        for (int o = 1; o < 32; o <<= 1) {
            int y = __shfl_up_sync(0xffffffffu, w, o);
            if (lane >= o) w += y;
        }
        wsum[lane] = w;
    }
    __syncthreads();
    int run = x - sum + (wid > 0 ? wsum[wid - 1] : 0);
    for (int i = 0; i < PER; ++i) {
        int idx = base + i;
        if (idx < N_NODES) {
            g_rowptr[idx] = run;
            g_cursor[idx] = run;
            run += g_counts[idx];
        }
    }
    if (t == 1023) g_rowptr[N_NODES] = run;

    // ---- degree counting-sort -> g_perm (balances hop warps) ----
    __shared__ int hist[128];
    if (t < 128) hist[t] = 0;
    __syncthreads();
    for (int i = 0; i < PER; ++i) {
        int idx = base + i;
        if (idx < N_NODES) {
            int d = min(g_counts[idx], 127);
            atomicAdd(&hist[d], 1);
        }
    }
    __syncthreads();
    if (t < 128) {
        // serial-ish exclusive prefix by warp 0..3 — small, do with one warp pair
    }
    // exclusive prefix over 128 bins using first 4 warps via shfl
    if (wid == 0) {
        // two chunks of 64 handled by simple loop in one thread for clarity
        if (lane == 0) {
            int acc2 = 0;
            for (int b = 0; b < 128; ++b) {
                int v = hist[b];
                hist[b] = acc2;
                acc2 += v;
            }
        }
    }
    __syncthreads();
    for (int i = 0; i < PER; ++i) {
        int idx = base + i;
        if (idx < N_NODES) {
            int d = min(g_counts[idx], 127);
            int r = atomicAdd(&hist[d], 1);
            g_perm[r] = idx;
        }
    }
}

// ================= dot body =================
// br0: r1 . h1   br1: r2 . h2   br2: r2 . bufA   (m3 = r2^T (A h3) / N)
__device__ __forceinline__ void dot_body(int br, int vb) {
    const float* rk = (br == 0) ? g_r1 : g_r2;
    const __half2* f2 = (br == 0) ? (const __half2*)g_h[0]
                      : (br == 1) ? (const __half2*)g_h[1]
                                  : (const __half2*)g_bufA;
    __shared__ float2 sm[4][64];
    int t = threadIdx.x;
    int d2 = t & 63, grp = t >> 6;
    int r0 = vb * 512 + grp * 128;
    int rend = min(r0 + 128, N_NODES);
    float2 s = make_float2(0.f, 0.f);
    for (int r = r0; r < rend; ++r) {
        float w = __ldg(&rk[r]);
        float2 x = __half22float2(f2[r * 64 + d2]);
        s.x += w * x.x; s.y += w * x.y;
    }
    sm[grp][d2] = s;
    __syncthreads();
    if (t < 64) {
        float2 tot = sm[0][t];
        tot.x += sm[1][t].x + sm[2][t].x + sm[3][t].x;
        tot.y += sm[1][t].y + sm[2][t].y + sm[3][t].y;
        atomicAdd(&g_dot[br * D + t * 2], tot.x);
        atomicAdd(&g_dot[br * D + t * 2 + 1], tot.y);
    }
}

// ================= K4: fill_r2 (8 edges/thread) || dot1 =================
__global__ __launch_bounds__(256) void k4_kernel(const int* __restrict__ erow,
                                                 const int* __restrict__ ecol,
                                                 const float* __restrict__ eval_) {
    int bx = blockIdx.x;
    if (bx < DOTG) {
        dot_body(0, bx);
        return;
    }
    int i = (bx - DOTG) * 256 + threadIdx.x;   // 8-edge packets
    if (i >= N_EDGES / 8) return;
    const int4* er4 = (const int4*)erow;
    const int4* ec4 = (const int4*)ecol;
    const float4* ev4 = (const float4*)eval_;
#pragma unroll
    for (int hh = 0; hh < 2; ++hh) {
        int q = i * 2 + hh;
        int4 r = er4[q];
        int4 c = ec4[q];
        float4 v = ev4[q];
        int p0 = atomicAdd(&g_cursor[r.x], 1);
        int p1 = atomicAdd(&g_cursor[r.y], 1);
        int p2 = atomicAdd(&g_cursor[r.z], 1);
        int p3 = atomicAdd(&g_cursor[r.w], 1);
        g_epack[p0] = make_uint2((unsigned)c.x, __float_as_uint(v.x));
        g_epack[p1] = make_uint2((unsigned)c.y, __float_as_uint(v.y));
        g_epack[p2] = make_uint2((unsigned)c.z, __float_as_uint(v.z));
        g_epack[p3] = make_uint2((unsigned)c.w, __float_as_uint(v.w));
        atomicAdd(&g_r2[c.x], v.x * __ldg(&g_r1[r.x]));
        atomicAdd(&g_r2[c.y], v.y * __ldg(&g_r1[r.y]));
        atomicAdd(&g_r2[c.z], v.z * __ldg(&g_r1[r.z]));
        atomicAdd(&g_r2[c.w], v.w * __ldg(&g_r1[r.w]));
    }
}

// ================= hop helpers =================
__device__ __forceinline__ void fma8x2(ull& a0, ull& a1, ull& a2, ull& a3,
                                       ull vv, uint4 q) {
    float2 f0 = __half22float2(*reinterpret_cast<const __half2*>(&q.x));
    float2 f1 = __half22float2(*reinterpret_cast<const __half2*>(&q.y));
    float2 f2 = __half22float2(*reinterpret_cast<const __half2*>(&q.z));
    float2 f3 = __half22float2(*reinterpret_cast<const __half2*>(&q.w));
    ull b0, b1, b2, b3;
    asm("mov.b64 %0,{%1,%2};" : "=l"(b0) : "f"(f0.x), "f"(f0.y));
    asm("mov.b64 %0,{%1,%2};" : "=l"(b1) : "f"(f1.x), "f"(f1.y));
    asm("mov.b64 %0,{%1,%2};" : "=l"(b2) : "f"(f2.x), "f"(f2.y));
    asm("mov.b64 %0,{%1,%2};" : "=l"(b3) : "f"(f3.x), "f"(f3.y));
    asm("fma.rn.f32x2 %0,%1,%2,%0;" : "+l"(a0) : "l"(vv), "l"(b0));
    asm("fma.rn.f32x2 %0,%1,%2,%0;" : "+l"(a1) : "l"(vv), "l"(b1));
    asm("fma.rn.f32x2 %0,%1,%2,%0;" : "+l"(a2) : "l"(vv), "l"(b2));
    asm("fma.rn.f32x2 %0,%1,%2,%0;" : "+l"(a3) : "l"(vv), "l"(b3));
}

__device__ __forceinline__ void unpack8(uint4 q, float* f) {
    float2 x;
    x = __half22float2(*(__half2*)&q.x); f[0] = x.x; f[1] = x.y;
    x = __half22float2(*(__half2*)&q.y); f[2] = x.x; f[3] = x.y;
    x = __half22float2(*(__half2*)&q.z); f[4] = x.x; f[5] = x.y;
    x = __half22float2(*(__half2*)&q.w); f[6] = x.x; f[7] = x.y;
}

__device__ __forceinline__ uint4 pack8(const float* a) {
    __half2 h0 = __floats2half2_rn(a[0], a[1]);
    __half2 h1 = __floats2half2_rn(a[2], a[3]);
    __half2 h2 = __floats2half2_rn(a[4], a[5]);
    __half2 h3 = __floats2half2_rn(a[6], a[7]);
    uint4 r;
    r.x = *(unsigned*)&h0; r.y = *(unsigned*)&h1;
    r.z = *(unsigned*)&h2; r.w = *(unsigned*)&h3;
    return r;
}

// ================= hop body (perm-balanced rows, two 8-deep gather groups) =====
// PHASE 1: bufA = A h3
// PHASE 2: bufA = A bufB + a1 (.) h1
// PHASE 3: out  = A bufA + cb  (fp32)
template <int PHASE>
__device__ __forceinline__ void hop_body(int blk, float* __restrict__ out) {
    const uint4* src = (PHASE == 1) ? (const uint4*)g_h[2]
                     : (PHASE == 2) ? (const uint4*)g_bufB
                                    : (const uint4*)g_bufA;

    int lane = threadIdx.x & 31;
    int warp = threadIdx.x >> 5;
    int hl = lane & 15;
    int halfsel = lane & 16;
    int rid = blk * 16 + warp * 2 + (lane >> 4);
    bool valid = rid < N_NODES;
    int row = valid ? __ldg(&g_perm[rid]) : 0;
    int s = valid ? __ldg(&g_rowptr[row]) : 0;
    int e = valid ? __ldg(&g_rowptr[row + 1]) : 0;
    int nb = (e - s + 15) >> 4;
    int nbmax = max(nb, __shfl_xor_sync(0xffffffffu, nb, 16));

    ull a0 = 0, a1 = 0, a2 = 0, a3 = 0;
    const uint4 z = make_uint4(0, 0, 0, 0);

    int idx0 = s + hl;
    uint2 p = (idx0 < e) ? __ldg(&g_epack[idx0]) : make_uint2(0, 0);

    for (int it = 0; it < nbmax; ++it) {
        int b = s + it * 16;
        int c = (int)p.x;
        float v = __uint_as_float(p.y);
        int nidx = b + 16 + hl;
        uint2 pn = (nidx < e) ? __ldg(&g_epack[nidx]) : make_uint2(0, 0);
        int cnt = min(16, max(0, e - b));
        int cmax = max(cnt, __shfl_xor_sync(0xffffffffu, cnt, 16));

        {
            uint4 q[8];
#pragma unroll
            for (int k = 0; k < 8; ++k) {
                int ck = __shfl_sync(0xffffffffu, c, halfsel | k);
                q[k] = (k < cnt) ? __ldg(&src[ck * 16 + hl]) : z;
            }
#pragma unroll
            for (int k = 0; k < 8; ++k) {
                float vk = __shfl_sync(0xffffffffu, v, halfsel | k);
                ull vv;
                asm("mov.b64 %0,{%1,%1};" : "=l"(vv) : "f"(vk));
                fma8x2(a0, a1, a2, a3, vv, q[k]);
            }
        }
        if (cmax > 8) {
            uint4 q[8];
#pragma unroll
            for (int k = 0; k < 8; ++k) {
                int ck = __shfl_sync(0xffffffffu, c, halfsel | (8 + k));
                q[k] = (8 + k < cnt) ? __ldg(&src[ck * 16 + hl]) : z;
            }
#pragma unroll
            for (int k = 0; k < 8; ++k) {
                float vk = __shfl_sync(0xffffffffu, v, halfsel | (8 + k));
                ull vv;
                asm("mov.b64 %0,{%1,%1};" : "=l"(vv) : "f"(vk));
                fma8x2(a0, a1, a2, a3, vv, q[k]);
            }
        }
        p = pn;
    }

    if (valid) {
        float a[8];
        asm("mov.b64 {%0,%1},%2;" : "=f"(a[0]), "=f"(a[1]) : "l"(a0));
        asm("mov.b64 {%0,%1},%2;" : "=f"(a[2]), "=f"(a[3]) : "l"(a1));
        asm("mov.b64 {%0,%1},%2;" : "=f"(a[4]), "=f"(a[5]) : "l"(a2));
        asm("mov.b64 {%0,%1},%2;" : "=f"(a[6]), "=f"(a[7]) : "l"(a3));
        int o = row * 16 + hl;
        if (PHASE == 1) {
            ((uint4*)g_bufA)[o] = pack8(a);
        } else if (PHASE == 2) {
            const float4* at1 = (const float4*)g_attn;
            float4 s10 = at1[hl * 2], s11 = at1[hl * 2 + 1];
            float f[8];
            unpack8(__ldg(&((const uint4*)g_h[0])[o]), f);
            a[0] = fmaf(s10.x, f[0], a[0]); a[1] = fmaf(s10.y, f[1], a[1]);
            a[2] = fmaf(s10.z, f[2], a[2]); a[3] = fmaf(s10.w, f[3], a[3]);
            a[4] = fmaf(s11.x, f[4], a[4]); a[5] = fmaf(s11.y, f[5], a[5]);
            a[6] = fmaf(s11.z, f[6], a[6]); a[7] = fmaf(s11.w, f[7], a[7]);
            ((uint4*)g_bufA)[o] = pack8(a);
        } else {
            const float4* cb4 = (const float4*)g_cb;
            float4 c0 = cb4[hl * 2], c1 = cb4[hl * 2 + 1];
            float4 oa = make_float4(a[0] + c0.x, a[1] + c0.y, a[2] + c0.z, a[3] + c0.w);
            float4 ob = make_float4(a[4] + c1.x, a[5] + c1.y, a[6] + c1.z, a[7] + c1.w);
            ((float4*)out)[row * 32 + hl * 2] = oa;
            ((float4*)out)[row * 32 + hl * 2 + 1] = ob;
        }
    }
}

// ================= K5: dot2 || hop1 (1 dot per 33-block group) ================
// grid = 98*33 = 3234
__global__ __launch_bounds__(256) void k5_kernel() {
    int bx = blockIdx.x;
    int grp = bx / 33, sl = bx % 33;
    if (sl == 0) {
        dot_body(1, grp);
    } else {
        int hb = grp * 32 + (sl - 1);
        if (hb < HOPG) hop_body<1>(hb, nullptr);
    }
}

// ================= K6: dot3 (r2 . bufA) + last-block MLP ======================
__global__ __launch_bounds__(256) void k6_kernel(const float* __restrict__ fc1w,
                                                 const float* __restrict__ fc1b,
                                                 const float* __restrict__ fc2w,
                                                 const float* __restrict__ fc2b,
                                                 const float* __restrict__ B1,
                                                 const float* __restrict__ B2,
                                                 const float* __restrict__ B3) {
    dot_body(2, blockIdx.x);
    __syncthreads();
    __shared__ int is_last;
    int t = threadIdx.x;
    if (t == 0) {
        __threadfence();
        is_last = (atomicAdd(&g_done, 1) == DOTG - 1) ? 1 : 0;
    }
    __syncthreads();
    if (!is_last) return;
    __threadfence();

    __shared__ float m[3 * D];
    __shared__ float t1[3 * D_RED];
    for (int i = t; i < 3 * D; i += 256) {
        int k = i >> 7, d = i & 127;
        const float* Bk = (k == 0) ? B1 : (k == 1) ? B2 : B3;
        m[i] = g_dot[i] * (1.0f / N_NODES) + Bk[d];
    }
    __syncthreads();
    if (t < 3 * D_RED) {
        int k = t / D_RED, r = t % D_RED;
        float s = fc1b[r];
        for (int d = 0; d < D; ++d) s = fmaf(m[k * D + d], fc1w[d * D_RED + r], s);
        t1[t] = s > 0.f ? s : 0.f;
    }
    __syncthreads();
    if (t < D) {
        float lg[3];
#pragma unroll
        for (int k = 0; k < 3; ++k) {
            float s = fc2b[t];
            for (int r = 0; r < D_RED; ++r) s = fmaf(t1[k * D_RED + r], fc2w[r * D + t], s);
            lg[k] = s;
        }
        float mx = fmaxf(lg[0], fmaxf(lg[1], lg[2]));
        float e0 = expf(lg[0] - mx), e1 = expf(lg[1] - mx), e2 = expf(lg[2] - mx);
        float inv = 1.f / (e0 + e1 + e2);
        float a0 = e0 * inv, a1 = e1 * inv, a2 = e2 * inv;
        g_attn[0 * D + t] = a0;
        g_attn[1 * D + t] = a1;
        g_attn[2 * D + t] = a2;
        g_cb[t] = a0 * B1[t] + a1 * B2[t] + a2 * B3[t];
    }
    if (t == 0) g_done = 0;
}

// ================= mix: bufB = a2 (.) h2 + a3 (.) bufA =================
__global__ __launch_bounds__(256) void mix_kernel() {
    int i = blockIdx.x * 256 + threadIdx.x;  // N_NODES*16 uint4 exact
    int hl = i & 15;
    const float4* a2 = (const float4*)(g_attn + 1 * D);
    const float4* a3 = (const float4*)(g_attn + 2 * D);
    float4 s20 = a2[hl * 2], s21 = a2[hl * 2 + 1];
    float4 s30 = a3[hl * 2], s31 = a3[hl * 2 + 1];
    float u[8], h[8];
    unpack8(((const uint4*)g_bufA)[i], u);
    unpack8(((const uint4*)g_h[1])[i], h);
    float r[8];
    r[0] = s20.x * h[0] + s30.x * u[0]; r[1] = s20.y * h[1] + s30.y * u[1];
    r[2] = s20.z * h[2] + s30.z * u[2]; r[3] = s20.w * h[3] + s30.w * u[3];
    r[4] = s21.x * h[4] + s31.x * u[4]; r[5] = s21.y * h[5] + s31.y * u[5];
    r[6] = s21.z * h[6] + s31.z * u[6]; r[7] = s21.w * h[7] + s31.w * u[7];
    ((uint4*)g_bufB)[i] = pack8(r);
}

// ================= hop2, hop3 =================
__global__ __launch_bounds__(256) void hop2_kernel() {
    hop_body<2>(blockIdx.x, nullptr);
}

__global__ __launch_bounds__(256) void hop3_kernel(float* __restrict__ out) {
    hop_body<3>(blockIdx.x, out);
}

// ================= launch =================
extern "C" void kernel_launch(void* const* d_in, const int* in_sizes, int n_in,
                              void* d_out, int out_size) {
    const float* features = (const float*)d_in[0];
    const int*   erow     = (const int*)d_in[1];
    const int*   ecol     = (const int*)d_in[2];
    const float* eval_    = (const float*)d_in[3];
    const float* W1 = (const float*)d_in[4];
    const float* B1 = (const float*)d_in[5];
    const float* W2 = (const float*)d_in[6];
    const float* B2 = (const float*)d_in[7];
    const float* W3 = (const float*)d_in[8];
    const float* B3 = (const float*)d_in[9];
    const float* fc1w = (const float*)d_in[10];
    const float* fc1b = (const float*)d_in[11];
    const float* fc2w = (const float*)d_in[12];
    const float* fc2b = (const float*)d_in[13];
    float* out = (float*)d_out;

    k1_kernel<<<244, 256>>>(W1, W2, W3);
    k2_kernel<<<EG * 4, 256>>>(features, erow, ecol, eval_);
    scan_kernel<<<1, 1024>>>();
    k4_kernel<<<DOTG + EG8, 256>>>(erow, ecol, eval_);
    k5_kernel<<<3234, 256>>>();
    k6_kernel<<<DOTG, 256>>>(fc1w, fc1b, fc2w, fc2b, B1, B2, B3);
    mix_kernel<<<HOPG, 256>>>();
    hop2_kernel<<<HOPG, 256>>>();
    hop3_kernel<<<HOPG, 256>>>(out);
}

// round 12
// speedup vs baseline: 1.1231x; 1.1231x over previous
#include <cuda_runtime.h>
#include <cuda_fp16.h>
#include <mma.h>
#include <math.h>

using namespace nvcuda;

typedef unsigned long long ull;

#define N_NODES 50000
#define N_PAD   50048
#define N_EDGES 800000
#define D 128
#define D_RED 32
#define EG 782          // ceil(200000/256) int4 edge blocks
#define EG8 391         // ceil(100000/256) 8-edge blocks
#define DOTG 98         // ceil(50000/512) dot blocks
#define HOPG 3125       // ceil(50000/16) hop blocks
#define LDMA 136        // skewed smem leading dim (halves)

// ---------------- scratch ----------------
__device__ __half g_x16[N_PAD * D];
__device__ __half g_w16[3][D * D];
__device__ __half g_h[3][N_PAD * D];
__device__ __half g_bufA[N_NODES * D];
__device__ __half g_bufB[N_NODES * D];
__device__ int    g_counts[N_NODES];
__device__ int    g_rowptr[N_NODES + 1];
__device__ int    g_cursor[N_NODES];
__device__ uint2  g_epack[N_EDGES];
__device__ float  g_r1[N_NODES];
__device__ float  g_r2[N_NODES];
__device__ float  g_dot[3 * D];
__device__ float  g_attn[3 * D];
__device__ float  g_cb[D];
__device__ int    g_done;

__device__ __forceinline__ float fast_tanh(float x) {
    float t = __expf(2.0f * x);
    return 1.0f - __fdividef(2.0f, t + 1.0f);
}

// ================= K1: zero + W->fp16 + X->fp16 =================
__global__ __launch_bounds__(256) void k1_kernel(const float* __restrict__ X,
                                                 const float* __restrict__ W1,
                                                 const float* __restrict__ W2,
                                                 const float* __restrict__ W3) {
    int bx = blockIdx.x, tid = threadIdx.x;
    if (bx < 196) {
        int i = bx * 256 + tid;
        if (i < N_NODES) {
            g_counts[i] = 0;
            g_r1[i] = 0.f; g_r2[i] = 0.f;
        }
        if (i < 3 * D) g_dot[i] = 0.f;
    } else if (bx < 244) {
        int idx = (bx - 196) * 256 + tid;
        int k = idx / 4096, o4 = idx % 4096;
        const float4* Wk4 = (const float4*)(k == 0 ? W1 : k == 1 ? W2 : W3);
        float4 w = Wk4[o4];
        __half2 h0 = __floats2half2_rn(w.x, w.y);
        __half2 h1 = __floats2half2_rn(w.z, w.w);
        ((uint2*)g_w16[k])[o4] = make_uint2(*(unsigned*)&h0, *(unsigned*)&h1);
    } else {
        int i = (bx - 244) * 256 + tid;
        if (i >= N_PAD * 16) return;
        int r = i >> 4;
        uint4 o = make_uint4(0, 0, 0, 0);
        if (r < N_NODES) {
            const float4* x4 = (const float4*)X;
            float4 f0 = x4[i * 2], f1 = x4[i * 2 + 1];
            __half2 h0 = __floats2half2_rn(f0.x, f0.y);
            __half2 h1 = __floats2half2_rn(f0.z, f0.w);
            __half2 h2 = __floats2half2_rn(f1.x, f1.y);
            __half2 h3 = __floats2half2_rn(f1.z, f1.w);
            o.x = *(unsigned*)&h0; o.y = *(unsigned*)&h1;
            o.z = *(unsigned*)&h2; o.w = *(unsigned*)&h3;
        }
        ((uint4*)g_x16)[i] = o;
    }
}

// ================= gemm body (skewed smem, B staged in 2 phases) =============
__device__ __forceinline__ void gemm_body(int k, int rb) {
    __shared__ __half As[64 * LDMA];   // 17408 B
    __shared__ __half Bs[64 * LDMA];   // 17408 B
    int tid = threadIdx.x;
    int row0 = rb * 64;
    __half* out = g_h[k];

    {
        const uint4* src = (const uint4*)(g_x16 + row0 * D);
        for (int i = tid; i < 64 * 16; i += 256) {
            int r = i >> 4, c4 = i & 15;
            *(uint4*)(As + r * LDMA + c4 * 8) = src[i];
        }
    }

    int warp = tid >> 5;
    int wr = warp >> 1;
    int wc0 = (warp & 1) * 4;

    wmma::fragment<wmma::accumulator, 16, 16, 16, float> acc[4];
#pragma unroll
    for (int c = 0; c < 4; ++c) wmma::fill_fragment(acc[c], 0.f);

#pragma unroll
    for (int ph = 0; ph < 2; ++ph) {
        __syncthreads();
        {
            const uint4* wsrc = (const uint4*)(g_w16[k] + ph * 64 * D);
            for (int i = tid; i < 64 * 16; i += 256) {
                int r = i >> 4, c4 = i & 15;
                *(uint4*)(Bs + r * LDMA + c4 * 8) = wsrc[i];
            }
        }
        __syncthreads();
#pragma unroll
        for (int k16 = 0; k16 < 4; ++k16) {
            wmma::fragment<wmma::matrix_a, 16, 16, 16, __half, wmma::row_major> a;
            wmma::load_matrix_sync(a, As + wr * 16 * LDMA + (ph * 4 + k16) * 16, LDMA);
#pragma unroll
            for (int c = 0; c < 4; ++c) {
                wmma::fragment<wmma::matrix_b, 16, 16, 16, __half, wmma::row_major> b;
                wmma::load_matrix_sync(b, Bs + k16 * 16 * LDMA + (wc0 + c) * 16, LDMA);
                wmma::mma_sync(acc[c], a, b, acc[c]);
            }
        }
    }
#pragma unroll
    for (int c = 0; c < 4; ++c) {
        wmma::fragment<wmma::accumulator, 16, 16, 16, __half> hacc;
#pragma unroll
        for (int i = 0; i < hacc.num_elements; ++i)
            hacc.x[i] = __float2half(fast_tanh(acc[c].x[i]));
        wmma::store_matrix_sync(out + (row0 + wr * 16) * D + (wc0 + c) * 16, hacc, D,
                                wmma::mem_row_major);
    }
}

// ================= K2: count_r1 || gemm, interleaved 1:3 =================
// grid = 782*4 = 3128
__global__ __launch_bounds__(256) void k2_kernel(const int* __restrict__ erow,
                                                 const int* __restrict__ ecol,
                                                 const float* __restrict__ eval_) {
    int grp = blockIdx.x >> 2, sl = blockIdx.x & 3;
    if (sl == 0) {
        int i = grp * 256 + threadIdx.x;
        if (i < N_EDGES / 4) {
            int4 r = ((const int4*)erow)[i];
            int4 c = ((const int4*)ecol)[i];
            float4 v = ((const float4*)eval_)[i];
            atomicAdd(&g_counts[r.x], 1);
            atomicAdd(&g_counts[r.y], 1);
            atomicAdd(&g_counts[r.z], 1);
            atomicAdd(&g_counts[r.w], 1);
            atomicAdd(&g_r1[c.x], v.x);
            atomicAdd(&g_r1[c.y], v.y);
            atomicAdd(&g_r1[c.z], v.z);
            atomicAdd(&g_r1[c.w], v.w);
        }
    } else {
        int gi = grp * 3 + (sl - 1);      // 0..2345
        gemm_body(gi / 782, gi % 782);
    }
}

// ================= K3: scan =================
__global__ void scan_kernel() {
    const int PER = 49;
    int t = threadIdx.x;
    int base = t * PER;
    int sum = 0;
    for (int i = 0; i < PER; ++i) {
        int idx = base + i;
        if (idx < N_NODES) sum += g_counts[idx];
    }
    int lane = t & 31, wid = t >> 5;
    int x = sum;
#pragma unroll
    for (int o = 1; o < 32; o <<= 1) {
        int y = __shfl_up_sync(0xffffffffu, x, o);
        if (lane >= o) x += y;
    }
    __shared__ int wsum[32];
    if (lane == 31) wsum[wid] = x;
    __syncthreads();
    if (wid == 0) {
        int w = wsum[lane];
#pragma unroll
        for (int o = 1; o < 32; o <<= 1) {
            int y = __shfl_up_sync(0xffffffffu, w, o);
            if (lane >= o) w += y;
        }
        wsum[lane] = w;
    }
    __syncthreads();
    int run = x - sum + (wid > 0 ? wsum[wid - 1] : 0);
    for (int i = 0; i < PER; ++i) {
        int idx = base + i;
        if (idx < N_NODES) {
            g_rowptr[idx] = run;
            g_cursor[idx] = run;
            run += g_counts[idx];
        }
    }
    if (t == 1023) g_rowptr[N_NODES] = run;
}

// ================= dot body =================
// br0: r1 . h1   br1: r2 . h2   br2: r2 . bufA   (m3 = r2^T (A h3) / N)
__device__ __forceinline__ void dot_body(int br, int vb) {
    const float* rk = (br == 0) ? g_r1 : g_r2;
    const __half2* f2 = (br == 0) ? (const __half2*)g_h[0]
                      : (br == 1) ? (const __half2*)g_h[1]
                                  : (const __half2*)g_bufA;
    __shared__ float2 sm[4][64];
    int t = threadIdx.x;
    int d2 = t & 63, grp = t >> 6;
    int r0 = vb * 512 + grp * 128;
    int rend = min(r0 + 128, N_NODES);
    float2 s = make_float2(0.f, 0.f);
    for (int r = r0; r < rend; ++r) {
        float w = __ldg(&rk[r]);
        float2 x = __half22float2(f2[r * 64 + d2]);
        s.x += w * x.x; s.y += w * x.y;
    }
    sm[grp][d2] = s;
    __syncthreads();
    if (t < 64) {
        float2 tot = sm[0][t];
        tot.x += sm[1][t].x + sm[2][t].x + sm[3][t].x;
        tot.y += sm[1][t].y + sm[2][t].y + sm[3][t].y;
        atomicAdd(&g_dot[br * D + t * 2], tot.x);
        atomicAdd(&g_dot[br * D + t * 2 + 1], tot.y);
    }
}

// ================= K4: dot1 || fill_r2 (8 edges/thread) =================
__global__ __launch_bounds__(256) void k4_kernel(const int* __restrict__ erow,
                                                 const int* __restrict__ ecol,
                                                 const float* __restrict__ eval_) {
    int bx = blockIdx.x;
    if (bx < DOTG) {
        dot_body(0, bx);
        return;
    }
    int i = (bx - DOTG) * 256 + threadIdx.x;   // 8-edge packets
    if (i >= N_EDGES / 8) return;
    const int4* er4 = (const int4*)erow;
    const int4* ec4 = (const int4*)ecol;
    const float4* ev4 = (const float4*)eval_;
#pragma unroll
    for (int hh = 0; hh < 2; ++hh) {
        int q = i * 2 + hh;
        int4 r = er4[q];
        int4 c = ec4[q];
        float4 v = ev4[q];
        int p0 = atomicAdd(&g_cursor[r.x], 1);
        int p1 = atomicAdd(&g_cursor[r.y], 1);
        int p2 = atomicAdd(&g_cursor[r.z], 1);
        int p3 = atomicAdd(&g_cursor[r.w], 1);
        g_epack[p0] = make_uint2((unsigned)c.x, __float_as_uint(v.x));
        g_epack[p1] = make_uint2((unsigned)c.y, __float_as_uint(v.y));
        g_epack[p2] = make_uint2((unsigned)c.z, __float_as_uint(v.z));
        g_epack[p3] = make_uint2((unsigned)c.w, __float_as_uint(v.w));
        atomicAdd(&g_r2[c.x], v.x * __ldg(&g_r1[r.x]));
        atomicAdd(&g_r2[c.y], v.y * __ldg(&g_r1[r.y]));
        atomicAdd(&g_r2[c.z], v.z * __ldg(&g_r1[r.z]));
        atomicAdd(&g_r2[c.w], v.w * __ldg(&g_r1[r.w]));
    }
}

// ================= hop helpers =================
__device__ __forceinline__ void fma8x2(ull& a0, ull& a1, ull& a2, ull& a3,
                                       ull vv, uint4 q) {
    float2 f0 = __half22float2(*reinterpret_cast<const __half2*>(&q.x));
    float2 f1 = __half22float2(*reinterpret_cast<const __half2*>(&q.y));
    float2 f2 = __half22float2(*reinterpret_cast<const __half2*>(&q.z));
    float2 f3 = __half22float2(*reinterpret_cast<const __half2*>(&q.w));
    ull b0, b1, b2, b3;
    asm("mov.b64 %0,{%1,%2};" : "=l"(b0) : "f"(f0.x), "f"(f0.y));
    asm("mov.b64 %0,{%1,%2};" : "=l"(b1) : "f"(f1.x), "f"(f1.y));
    asm("mov.b64 %0,{%1,%2};" : "=l"(b2) : "f"(f2.x), "f"(f2.y));
    asm("mov.b64 %0,{%1,%2};" : "=l"(b3) : "f"(f3.x), "f"(f3.y));
    asm("fma.rn.f32x2 %0,%1,%2,%0;" : "+l"(a0) : "l"(vv), "l"(b0));
    asm("fma.rn.f32x2 %0,%1,%2,%0;" : "+l"(a1) : "l"(vv), "l"(b1));
    asm("fma.rn.f32x2 %0,%1,%2,%0;" : "+l"(a2) : "l"(vv), "l"(b2));
    asm("fma.rn.f32x2 %0,%1,%2,%0;" : "+l"(a3) : "l"(vv), "l"(b3));
}

__device__ __forceinline__ void unpack8(uint4 q, float* f) {
    float2 x;
    x = __half22float2(*(__half2*)&q.x); f[0] = x.x; f[1] = x.y;
    x = __half22float2(*(__half2*)&q.y); f[2] = x.x; f[3] = x.y;
    x = __half22float2(*(__half2*)&q.z); f[4] = x.x; f[5] = x.y;
    x = __half22float2(*(__half2*)&q.w); f[6] = x.x; f[7] = x.y;
}

__device__ __forceinline__ uint4 pack8(const float* a) {
    __half2 h0 = __floats2half2_rn(a[0], a[1]);
    __half2 h1 = __floats2half2_rn(a[2], a[3]);
    __half2 h2 = __floats2half2_rn(a[4], a[5]);
    __half2 h3 = __floats2half2_rn(a[6], a[7]);
    uint4 r;
    r.x = *(unsigned*)&h0; r.y = *(unsigned*)&h1;
    r.z = *(unsigned*)&h2; r.w = *(unsigned*)&h3;
    return r;
}

// ================= hop body: peeled loop, unpredicated full iterations =========
// Invalid lanes carry (c,v)=(0,0): gather hits row 0 (L1-hot), FMA adds 0.
// PHASE 1: bufA = A h3
// PHASE 2: bufA = A bufB + a1 (.) h1
// PHASE 3: out  = A bufA + cb  (fp32)
template <int PHASE>
__device__ __forceinline__ void hop_body(int blk, float* __restrict__ out) {
    const uint4* src = (PHASE == 1) ? (const uint4*)g_h[2]
                     : (PHASE == 2) ? (const uint4*)g_bufB
                                    : (const uint4*)g_bufA;

    int lane = threadIdx.x & 31;
    int warp = threadIdx.x >> 5;
    int hl = lane & 15;
    int halfsel = lane & 16;
    int row = blk * 16 + warp * 2 + (lane >> 4);
    bool valid = row < N_NODES;
    int s = valid ? g_rowptr[row] : 0;
    int e = valid ? g_rowptr[row + 1] : 0;
    int deg = e - s;
    int nb = (deg + 15) >> 4;
    int nbmax = max(nb, __shfl_xor_sync(0xffffffffu, nb, 16));

    ull a0 = 0, a1 = 0, a2 = 0, a3 = 0;

    int idx0 = s + hl;
    uint2 p = (idx0 < e) ? __ldg(&g_epack[idx0]) : make_uint2(0, 0);

    // full iterations: no bounds logic at all
    int it = 0;
    for (; it + 1 < nbmax; ++it) {
        int c = (int)p.x;
        float v = __uint_as_float(p.y);
        int nidx = s + (it + 1) * 16 + hl;
        p = (nidx < e) ? __ldg(&g_epack[nidx]) : make_uint2(0, 0);

        uint4 q[8];
#pragma unroll
        for (int k = 0; k < 8; ++k) {
            int ck = __shfl_sync(0xffffffffu, c, halfsel | k);
            q[k] = __ldg(&src[ck * 16 + hl]);
        }
#pragma unroll
        for (int k = 0; k < 8; ++k) {
            float vk = __shfl_sync(0xffffffffu, v, halfsel | k);
            ull vv;
            asm("mov.b64 %0,{%1,%1};" : "=l"(vv) : "f"(vk));
            fma8x2(a0, a1, a2, a3, vv, q[k]);
        }
#pragma unroll
        for (int k = 8; k < 16; ++k) {
            int ck = __shfl_sync(0xffffffffu, c, halfsel | k);
            q[k - 8] = __ldg(&src[ck * 16 + hl]);
        }
#pragma unroll
        for (int k = 8; k < 16; ++k) {
            float vk = __shfl_sync(0xffffffffu, v, halfsel | k);
            ull vv;
            asm("mov.b64 %0,{%1,%1};" : "=l"(vv) : "f"(vk));
            fma8x2(a0, a1, a2, a3, vv, q[k - 8]);
        }
    }
    // last iteration: gate second group by remaining-count across the pair
    if (nbmax > 0) {
        int c = (int)p.x;
        float v = __uint_as_float(p.y);
        int rem = deg - it * 16;
        int remmax = max(rem, __shfl_xor_sync(0xffffffffu, rem, 16));

        uint4 q[8];
#pragma unroll
        for (int k = 0; k < 8; ++k) {
            int ck = __shfl_sync(0xffffffffu, c, halfsel | k);
            q[k] = __ldg(&src[ck * 16 + hl]);
        }
#pragma unroll
        for (int k = 0; k < 8; ++k) {
            float vk = __shfl_sync(0xffffffffu, v, halfsel | k);
            ull vv;
            asm("mov.b64 %0,{%1,%1};" : "=l"(vv) : "f"(vk));
            fma8x2(a0, a1, a2, a3, vv, q[k]);
        }
        if (remmax > 8) {
#pragma unroll
            for (int k = 8; k < 16; ++k) {
                int ck = __shfl_sync(0xffffffffu, c, halfsel | k);
                q[k - 8] = __ldg(&src[ck * 16 + hl]);
            }
#pragma unroll
            for (int k = 8; k < 16; ++k) {
                float vk = __shfl_sync(0xffffffffu, v, halfsel | k);
                ull vv;
                asm("mov.b64 %0,{%1,%1};" : "=l"(vv) : "f"(vk));
                fma8x2(a0, a1, a2, a3, vv, q[k - 8]);
            }
        }
    }

    if (valid) {
        float a[8];
        asm("mov.b64 {%0,%1},%2;" : "=f"(a[0]), "=f"(a[1]) : "l"(a0));
        asm("mov.b64 {%0,%1},%2;" : "=f"(a[2]), "=f"(a[3]) : "l"(a1));
        asm("mov.b64 {%0,%1},%2;" : "=f"(a[4]), "=f"(a[5]) : "l"(a2));
        asm("mov.b64 {%0,%1},%2;" : "=f"(a[6]), "=f"(a[7]) : "l"(a3));
        int o = row * 16 + hl;
        if (PHASE == 1) {
            ((uint4*)g_bufA)[o] = pack8(a);
        } else if (PHASE == 2) {
            const float4* at1 = (const float4*)g_attn;
            float4 s10 = at1[hl * 2], s11 = at1[hl * 2 + 1];
            float f[8];
            unpack8(__ldg(&((const uint4*)g_h[0])[o]), f);
            a[0] = fmaf(s10.x, f[0], a[0]); a[1] = fmaf(s10.y, f[1], a[1]);
            a[2] = fmaf(s10.z, f[2], a[2]); a[3] = fmaf(s10.w, f[3], a[3]);
            a[4] = fmaf(s11.x, f[4], a[4]); a[5] = fmaf(s11.y, f[5], a[5]);
            a[6] = fmaf(s11.z, f[6], a[6]); a[7] = fmaf(s11.w, f[7], a[7]);
            ((uint4*)g_bufA)[o] = pack8(a);
        } else {
            const float4* cb4 = (const float4*)g_cb;
            float4 c0 = cb4[hl * 2], c1 = cb4[hl * 2 + 1];
            float4 oa = make_float4(a[0] + c0.x, a[1] + c0.y, a[2] + c0.z, a[3] + c0.w);
            float4 ob = make_float4(a[4] + c1.x, a[5] + c1.y, a[6] + c1.z, a[7] + c1.w);
            ((float4*)out)[row * 32 + hl * 2] = oa;
            ((float4*)out)[row * 32 + hl * 2 + 1] = ob;
        }
    }
}

// ================= K5: dot2 || hop1 (1 dot per 33-block group) ================
// grid = 98*33 = 3234
__global__ __launch_bounds__(256) void k5_kernel() {
    int bx = blockIdx.x;
    int grp = bx / 33, sl = bx % 33;
    if (sl == 0) {
        dot_body(1, grp);
    } else {
        int hb = grp * 32 + (sl - 1);
        if (hb < HOPG) hop_body<1>(hb, nullptr);
    }
}

// ================= K6: dot3 (r2 . bufA) + last-block MLP ======================
__global__ __launch_bounds__(256) void k6_kernel(const float* __restrict__ fc1w,
                                                 const float* __restrict__ fc1b,
                                                 const float* __restrict__ fc2w,
                                                 const float* __restrict__ fc2b,
                                                 const float* __restrict__ B1,
                                                 const float* __restrict__ B2,
                                                 const float* __restrict__ B3) {
    dot_body(2, blockIdx.x);
    __syncthreads();
    __shared__ int is_last;
    int t = threadIdx.x;
    if (t == 0) {
        __threadfence();
        is_last = (atomicAdd(&g_done, 1) == DOTG - 1) ? 1 : 0;
    }
    __syncthreads();
    if (!is_last) return;
    __threadfence();

    __shared__ float m[3 * D];
    __shared__ float t1[3 * D_RED];
    for (int i = t; i < 3 * D; i += 256) {
        int k = i >> 7, d = i & 127;
        const float* Bk = (k == 0) ? B1 : (k == 1) ? B2 : B3;
        m[i] = g_dot[i] * (1.0f / N_NODES) + Bk[d];
    }
    __syncthreads();
    if (t < 3 * D_RED) {
        int k = t / D_RED, r = t % D_RED;
        float s = fc1b[r];
        for (int d = 0; d < D; ++d) s = fmaf(m[k * D + d], fc1w[d * D_RED + r], s);
        t1[t] = s > 0.f ? s : 0.f;
    }
    __syncthreads();
    if (t < D) {
        float lg[3];
#pragma unroll
        for (int k = 0; k < 3; ++k) {
            float s = fc2b[t];
            for (int r = 0; r < D_RED; ++r) s = fmaf(t1[k * D_RED + r], fc2w[r * D + t], s);
            lg[k] = s;
        }
        float mx = fmaxf(lg[0], fmaxf(lg[1], lg[2]));
        float e0 = expf(lg[0] - mx), e1 = expf(lg[1] - mx), e2 = expf(lg[2] - mx);
        float inv = 1.f / (e0 + e1 + e2);
        float a0 = e0 * inv, a1 = e1 * inv, a2 = e2 * inv;
        g_attn[0 * D + t] = a0;
        g_attn[1 * D + t] = a1;
        g_attn[2 * D + t] = a2;
        g_cb[t] = a0 * B1[t] + a1 * B2[t] + a2 * B3[t];
    }
    if (t == 0) g_done = 0;
}

// ================= mix: bufB = a2 (.) h2 + a3 (.) bufA =================
__global__ __launch_bounds__(256) void mix_kernel() {
    int i = blockIdx.x * 256 + threadIdx.x;  // N_NODES*16 uint4 exact
    int hl = i & 15;
    const float4* a2 = (const float4*)(g_attn + 1 * D);
    const float4* a3 = (const float4*)(g_attn + 2 * D);
    float4 s20 = a2[hl * 2], s21 = a2[hl * 2 + 1];
    float4 s30 = a3[hl * 2], s31 = a3[hl * 2 + 1];
    float u[8], h[8];
    unpack8(((const uint4*)g_bufA)[i], u);
    unpack8(((const uint4*)g_h[1])[i], h);
    float r[8];
    r[0] = s20.x * h[0] + s30.x * u[0]; r[1] = s20.y * h[1] + s30.y * u[1];
    r[2] = s20.z * h[2] + s30.z * u[2]; r[3] = s20.w * h[3] + s30.w * u[3];
    r[4] = s21.x * h[4] + s31.x * u[4]; r[5] = s21.y * h[5] + s31.y * u[5];
    r[6] = s21.z * h[6] + s31.z * u[6]; r[7] = s21.w * h[7] + s31.w * u[7];
    ((uint4*)g_bufB)[i] = pack8(r);
}

// ================= hop2, hop3 =================
__global__ __launch_bounds__(256) void hop2_kernel() {
    hop_body<2>(blockIdx.x, nullptr);
}

__global__ __launch_bounds__(256) void hop3_kernel(float* __restrict__ out) {
    hop_body<3>(blockIdx.x, out);
}

// ================= launch =================
extern "C" void kernel_launch(void* const* d_in, const int* in_sizes, int n_in,
                              void* d_out, int out_size) {
    const float* features = (const float*)d_in[0];
    const int*   erow     = (const int*)d_in[1];
    const int*   ecol     = (const int*)d_in[2];
    const float* eval_    = (const float*)d_in[3];
    const float* W1 = (const float*)d_in[4];
    const float* B1 = (const float*)d_in[5];
    const float* W2 = (const float*)d_in[6];
    const float* B2 = (const float*)d_in[7];
    const float* W3 = (const float*)d_in[8];
    const float* B3 = (const float*)d_in[9];
    const float* fc1w = (const float*)d_in[10];
    const float* fc1b = (const float*)d_in[11];
    const float* fc2w = (const float*)d_in[12];
    const float* fc2b = (const float*)d_in[13];
    float* out = (float*)d_out;

    k1_kernel<<<196 + 48 + 3128, 256>>>(features, W1, W2, W3);
    k2_kernel<<<EG * 4, 256>>>(erow, ecol, eval_);
    scan_kernel<<<1, 1024>>>();
    k4_kernel<<<DOTG + EG8, 256>>>(erow, ecol, eval_);
    k5_kernel<<<3234, 256>>>();
    k6_kernel<<<DOTG, 256>>>(fc1w, fc1b, fc2w, fc2b, B1, B2, B3);
    mix_kernel<<<HOPG, 256>>>();
    hop2_kernel<<<HOPG, 256>>>();
    hop3_kernel<<<HOPG, 256>>>(out);
}

// round 13
// speedup vs baseline: 1.1774x; 1.0484x over previous
#include <cuda_runtime.h>
#include <cuda_fp16.h>
#include <mma.h>
#include <math.h>

using namespace nvcuda;

typedef unsigned long long ull;

#define N_NODES 50000
#define N_PAD   50048
#define N_EDGES 800000
#define D 128
#define D_RED 32
#define EG 782          // ceil(200000/256) int4 edge blocks
#define EG8 391         // ceil(100000/256) 8-edge blocks
#define DOTG 98         // ceil(50000/512) dot blocks
#define HOPG 3125       // ceil(50000/16) hop blocks
#define XCG 3128        // N_PAD*16/256 x-convert blocks
#define LDMA 136        // skewed smem leading dim (halves)

// ---------------- scratch ----------------
__device__ __half g_x16[N_PAD * D];
__device__ __half g_w16[3][D * D];
__device__ __half g_h[3][N_PAD * D];
__device__ __half g_bufA[N_NODES * D];
__device__ __half g_bufB[N_NODES * D];
__device__ int    g_counts[N_NODES];
__device__ int    g_rowptr[N_NODES + 1];
__device__ int    g_cursor[N_NODES];
__device__ uint2  g_epack[N_EDGES];
__device__ float  g_r1[N_NODES];
__device__ float  g_r2[N_NODES];
__device__ float  g_dot[3 * D];
__device__ float  g_attn[3 * D];
__device__ float  g_cb[D];
__device__ int    g_done;

__device__ __forceinline__ float fast_tanh(float x) {
    float t = __expf(2.0f * x);
    return 1.0f - __fdividef(2.0f, t + 1.0f);
}

// ================= K1: Xcvt || count_r1 || Wcvt =================
// grid = 782*5 + 48 = 3958.  bx<3910: (bx%5==0 -> count, else xcvt); tail: Wcvt.
__global__ __launch_bounds__(256) void k1_kernel(const float* __restrict__ X,
                                                 const float* __restrict__ W1,
                                                 const float* __restrict__ W2,
                                                 const float* __restrict__ W3,
                                                 const int* __restrict__ erow,
                                                 const int* __restrict__ ecol,
                                                 const float* __restrict__ eval_) {
    int bx = blockIdx.x, tid = threadIdx.x;
    if (bx >= 3910) {
        int idx = (bx - 3910) * 256 + tid;   // 12288 float4s
        int k = idx / 4096, o4 = idx % 4096;
        const float4* Wk4 = (const float4*)(k == 0 ? W1 : k == 1 ? W2 : W3);
        float4 w = Wk4[o4];
        __half2 h0 = __floats2half2_rn(w.x, w.y);
        __half2 h1 = __floats2half2_rn(w.z, w.w);
        ((uint2*)g_w16[k])[o4] = make_uint2(*(unsigned*)&h0, *(unsigned*)&h1);
        return;
    }
    int grp = bx / 5, sl = bx % 5;
    if (sl == 0) {
        // count + r1 (state pre-zeroed by previous launch's hop3 tail)
        int i = grp * 256 + tid;
        if (i < N_EDGES / 4) {
            int4 r = ((const int4*)erow)[i];
            int4 c = ((const int4*)ecol)[i];
            float4 v = ((const float4*)eval_)[i];
            atomicAdd(&g_counts[r.x], 1);
            atomicAdd(&g_counts[r.y], 1);
            atomicAdd(&g_counts[r.z], 1);
            atomicAdd(&g_counts[r.w], 1);
            atomicAdd(&g_r1[c.x], v.x);
            atomicAdd(&g_r1[c.y], v.y);
            atomicAdd(&g_r1[c.z], v.z);
            atomicAdd(&g_r1[c.w], v.w);
        }
    } else {
        int i = (grp * 4 + (sl - 1)) * 256 + tid;   // over N_PAD*16 uint4, exact
        int r = i >> 4;
        uint4 o = make_uint4(0, 0, 0, 0);
        if (r < N_NODES) {
            const float4* x4 = (const float4*)X;
            float4 f0 = x4[i * 2], f1 = x4[i * 2 + 1];
            __half2 h0 = __floats2half2_rn(f0.x, f0.y);
            __half2 h1 = __floats2half2_rn(f0.z, f0.w);
            __half2 h2 = __floats2half2_rn(f1.x, f1.y);
            __half2 h3 = __floats2half2_rn(f1.z, f1.w);
            o.x = *(unsigned*)&h0; o.y = *(unsigned*)&h1;
            o.z = *(unsigned*)&h2; o.w = *(unsigned*)&h3;
        }
        ((uint4*)g_x16)[i] = o;
    }
}

// ================= gemm body (skewed smem, B staged in 2 phases) =============
__device__ __forceinline__ void gemm_body(int k, int rb) {
    __shared__ __half As[64 * LDMA];   // 17408 B
    __shared__ __half Bs[64 * LDMA];   // 17408 B
    int tid = threadIdx.x;
    int row0 = rb * 64;
    __half* out = g_h[k];

    {
        const uint4* src = (const uint4*)(g_x16 + row0 * D);
        for (int i = tid; i < 64 * 16; i += 256) {
            int r = i >> 4, c4 = i & 15;
            *(uint4*)(As + r * LDMA + c4 * 8) = src[i];
        }
    }

    int warp = tid >> 5;
    int wr = warp >> 1;
    int wc0 = (warp & 1) * 4;

    wmma::fragment<wmma::accumulator, 16, 16, 16, float> acc[4];
#pragma unroll
    for (int c = 0; c < 4; ++c) wmma::fill_fragment(acc[c], 0.f);

#pragma unroll
    for (int ph = 0; ph < 2; ++ph) {
        __syncthreads();
        {
            const uint4* wsrc = (const uint4*)(g_w16[k] + ph * 64 * D);
            for (int i = tid; i < 64 * 16; i += 256) {
                int r = i >> 4, c4 = i & 15;
                *(uint4*)(Bs + r * LDMA + c4 * 8) = wsrc[i];
            }
        }
        __syncthreads();
#pragma unroll
        for (int k16 = 0; k16 < 4; ++k16) {
            wmma::fragment<wmma::matrix_a, 16, 16, 16, __half, wmma::row_major> a;
            wmma::load_matrix_sync(a, As + wr * 16 * LDMA + (ph * 4 + k16) * 16, LDMA);
#pragma unroll
            for (int c = 0; c < 4; ++c) {
                wmma::fragment<wmma::matrix_b, 16, 16, 16, __half, wmma::row_major> b;
                wmma::load_matrix_sync(b, Bs + k16 * 16 * LDMA + (wc0 + c) * 16, LDMA);
                wmma::mma_sync(acc[c], a, b, acc[c]);
            }
        }
    }
#pragma unroll
    for (int c = 0; c < 4; ++c) {
        wmma::fragment<wmma::accumulator, 16, 16, 16, __half> hacc;
#pragma unroll
        for (int i = 0; i < hacc.num_elements; ++i)
            hacc.x[i] = __float2half(fast_tanh(acc[c].x[i]));
        wmma::store_matrix_sync(out + (row0 + wr * 16) * D + (wc0 + c) * 16, hacc, D,
                                wmma::mem_row_major);
    }
}

// ================= K2: gemm k=0,1 =================
__global__ __launch_bounds__(256) void k2_kernel() {
    gemm_body(blockIdx.x / 782, blockIdx.x % 782);
}

// ================= K3: scan (1 block) || gemm k=2 (782 blocks) =================
__global__ __launch_bounds__(256) void scan_kernel() {
    if (blockIdx.x > 0) {
        gemm_body(2, blockIdx.x - 1);
        return;
    }
    // 256-thread scan: each thread owns 49 int4 = 196 counts
    const int P4 = 49;
    const int TOT4 = N_NODES / 4;   // 12500
    int t = threadIdx.x;
    int sum = 0;
    for (int i = 0; i < P4; ++i) {
        int idx4 = t * P4 + i;
        if (idx4 < TOT4) {
            int4 c = ((const int4*)g_counts)[idx4];
            sum += c.x + c.y + c.z + c.w;
        }
    }
    int lane = t & 31, wid = t >> 5;
    int x = sum;
#pragma unroll
    for (int o = 1; o < 32; o <<= 1) {
        int y = __shfl_up_sync(0xffffffffu, x, o);
        if (lane >= o) x += y;
    }
    __shared__ int wsum[8];
    if (lane == 31) wsum[wid] = x;
    __syncthreads();
    if (wid == 0 && lane < 8) {
        int w = wsum[lane];
#pragma unroll
        for (int o = 1; o < 8; o <<= 1) {
            int y = __shfl_up_sync(0xffu, w, o);
            if (lane >= o) w += y;
        }
        wsum[lane] = w;
    }
    __syncthreads();
    int run = x - sum + (wid > 0 ? wsum[wid - 1] : 0);
    for (int i = 0; i < P4; ++i) {
        int idx4 = t * P4 + i;
        if (idx4 < TOT4) {
            int4 c = ((const int4*)g_counts)[idx4];
            int b = idx4 * 4;
            g_rowptr[b] = run;     g_cursor[b] = run;     run += c.x;
            g_rowptr[b + 1] = run; g_cursor[b + 1] = run; run += c.y;
            g_rowptr[b + 2] = run; g_cursor[b + 2] = run; run += c.z;
            g_rowptr[b + 3] = run; g_cursor[b + 3] = run; run += c.w;
        }
    }
    if (t == 0) g_rowptr[N_NODES] = N_EDGES;
}

// ================= dot body =================
// br0: r1 . h1   br1: r2 . h2   br2: r2 . bufA   (m3 = r2^T (A h3) / N)
__device__ __forceinline__ void dot_body(int br, int vb) {
    const float* rk = (br == 0) ? g_r1 : g_r2;
    const __half2* f2 = (br == 0) ? (const __half2*)g_h[0]
                      : (br == 1) ? (const __half2*)g_h[1]
                                  : (const __half2*)g_bufA;
    __shared__ float2 sm[4][64];
    int t = threadIdx.x;
    int d2 = t & 63, grp = t >> 6;
    int r0 = vb * 512 + grp * 128;
    int rend = min(r0 + 128, N_NODES);
    float2 s = make_float2(0.f, 0.f);
    for (int r = r0; r < rend; ++r) {
        float w = __ldg(&rk[r]);
        float2 x = __half22float2(f2[r * 64 + d2]);
        s.x += w * x.x; s.y += w * x.y;
    }
    sm[grp][d2] = s;
    __syncthreads();
    if (t < 64) {
        float2 tot = sm[0][t];
        tot.x += sm[1][t].x + sm[2][t].x + sm[3][t].x;
        tot.y += sm[1][t].y + sm[2][t].y + sm[3][t].y;
        atomicAdd(&g_dot[br * D + t * 2], tot.x);
        atomicAdd(&g_dot[br * D + t * 2 + 1], tot.y);
    }
}

// ================= K4: dot1 || fill_r2 (8 edges/thread) =================
__global__ __launch_bounds__(256) void k4_kernel(const int* __restrict__ erow,
                                                 const int* __restrict__ ecol,
                                                 const float* __restrict__ eval_) {
    int bx = blockIdx.x;
    if (bx < DOTG) {
        dot_body(0, bx);
        return;
    }
    int i = (bx - DOTG) * 256 + threadIdx.x;   // 8-edge packets
    if (i >= N_EDGES / 8) return;
    const int4* er4 = (const int4*)erow;
    const int4* ec4 = (const int4*)ecol;
    const float4* ev4 = (const float4*)eval_;
#pragma unroll
    for (int hh = 0; hh < 2; ++hh) {
        int q = i * 2 + hh;
        int4 r = er4[q];
        int4 c = ec4[q];
        float4 v = ev4[q];
        int p0 = atomicAdd(&g_cursor[r.x], 1);
        int p1 = atomicAdd(&g_cursor[r.y], 1);
        int p2 = atomicAdd(&g_cursor[r.z], 1);
        int p3 = atomicAdd(&g_cursor[r.w], 1);
        g_epack[p0] = make_uint2((unsigned)c.x, __float_as_uint(v.x));
        g_epack[p1] = make_uint2((unsigned)c.y, __float_as_uint(v.y));
        g_epack[p2] = make_uint2((unsigned)c.z, __float_as_uint(v.z));
        g_epack[p3] = make_uint2((unsigned)c.w, __float_as_uint(v.w));
        atomicAdd(&g_r2[c.x], v.x * __ldg(&g_r1[r.x]));
        atomicAdd(&g_r2[c.y], v.y * __ldg(&g_r1[r.y]));
        atomicAdd(&g_r2[c.z], v.z * __ldg(&g_r1[r.z]));
        atomicAdd(&g_r2[c.w], v.w * __ldg(&g_r1[r.w]));
    }
}

// ================= hop helpers =================
__device__ __forceinline__ void fma8x2(ull& a0, ull& a1, ull& a2, ull& a3,
                                       ull vv, uint4 q) {
    float2 f0 = __half22float2(*reinterpret_cast<const __half2*>(&q.x));
    float2 f1 = __half22float2(*reinterpret_cast<const __half2*>(&q.y));
    float2 f2 = __half22float2(*reinterpret_cast<const __half2*>(&q.z));
    float2 f3 = __half22float2(*reinterpret_cast<const __half2*>(&q.w));
    ull b0, b1, b2, b3;
    asm("mov.b64 %0,{%1,%2};" : "=l"(b0) : "f"(f0.x), "f"(f0.y));
    asm("mov.b64 %0,{%1,%2};" : "=l"(b1) : "f"(f1.x), "f"(f1.y));
    asm("mov.b64 %0,{%1,%2};" : "=l"(b2) : "f"(f2.x), "f"(f2.y));
    asm("mov.b64 %0,{%1,%2};" : "=l"(b3) : "f"(f3.x), "f"(f3.y));
    asm("fma.rn.f32x2 %0,%1,%2,%0;" : "+l"(a0) : "l"(vv), "l"(b0));
    asm("fma.rn.f32x2 %0,%1,%2,%0;" : "+l"(a1) : "l"(vv), "l"(b1));
    asm("fma.rn.f32x2 %0,%1,%2,%0;" : "+l"(a2) : "l"(vv), "l"(b2));
    asm("fma.rn.f32x2 %0,%1,%2,%0;" : "+l"(a3) : "l"(vv), "l"(b3));
}

__device__ __forceinline__ void unpack8(uint4 q, float* f) {
    float2 x;
    x = __half22float2(*(__half2*)&q.x); f[0] = x.x; f[1] = x.y;
    x = __half22float2(*(__half2*)&q.y); f[2] = x.x; f[3] = x.y;
    x = __half22float2(*(__half2*)&q.z); f[4] = x.x; f[5] = x.y;
    x = __half22float2(*(__half2*)&q.w); f[6] = x.x; f[7] = x.y;
}

__device__ __forceinline__ uint4 pack8(const float* a) {
    __half2 h0 = __floats2half2_rn(a[0], a[1]);
    __half2 h1 = __floats2half2_rn(a[2], a[3]);
    __half2 h2 = __floats2half2_rn(a[4], a[5]);
    __half2 h3 = __floats2half2_rn(a[6], a[7]);
    uint4 r;
    r.x = *(unsigned*)&h0; r.y = *(unsigned*)&h1;
    r.z = *(unsigned*)&h2; r.w = *(unsigned*)&h3;
    return r;
}

// ================= hop body: peeled loop, unpredicated full iterations =========
// PHASE 1: bufA = A h3
// PHASE 2: bufA = A bufB + a1 (.) h1
// PHASE 3: out  = A bufA + cb  (fp32)
template <int PHASE>
__device__ __forceinline__ void hop_body(int blk, float* __restrict__ out) {
    const uint4* src = (PHASE == 1) ? (const uint4*)g_h[2]
                     : (PHASE == 2) ? (const uint4*)g_bufB
                                    : (const uint4*)g_bufA;

    int lane = threadIdx.x & 31;
    int warp = threadIdx.x >> 5;
    int hl = lane & 15;
    int halfsel = lane & 16;
    int row = blk * 16 + warp * 2 + (lane >> 4);
    bool valid = row < N_NODES;
    int s = valid ? g_rowptr[row] : 0;
    int e = valid ? g_rowptr[row + 1] : 0;
    int deg = e - s;
    int nb = (deg + 15) >> 4;
    int nbmax = max(nb, __shfl_xor_sync(0xffffffffu, nb, 16));

    ull a0 = 0, a1 = 0, a2 = 0, a3 = 0;

    int idx0 = s + hl;
    uint2 p = (idx0 < e) ? __ldg(&g_epack[idx0]) : make_uint2(0, 0);

    int it = 0;
    for (; it + 1 < nbmax; ++it) {
        int c = (int)p.x;
        float v = __uint_as_float(p.y);
        int nidx = s + (it + 1) * 16 + hl;
        p = (nidx < e) ? __ldg(&g_epack[nidx]) : make_uint2(0, 0);

        uint4 q[8];
#pragma unroll
        for (int k = 0; k < 8; ++k) {
            int ck = __shfl_sync(0xffffffffu, c, halfsel | k);
            q[k] = __ldg(&src[ck * 16 + hl]);
        }
#pragma unroll
        for (int k = 0; k < 8; ++k) {
            float vk = __shfl_sync(0xffffffffu, v, halfsel | k);
            ull vv;
            asm("mov.b64 %0,{%1,%1};" : "=l"(vv) : "f"(vk));
            fma8x2(a0, a1, a2, a3, vv, q[k]);
        }
#pragma unroll
        for (int k = 8; k < 16; ++k) {
            int ck = __shfl_sync(0xffffffffu, c, halfsel | k);
            q[k - 8] = __ldg(&src[ck * 16 + hl]);
        }
#pragma unroll
        for (int k = 8; k < 16; ++k) {
            float vk = __shfl_sync(0xffffffffu, v, halfsel | k);
            ull vv;
            asm("mov.b64 %0,{%1,%1};" : "=l"(vv) : "f"(vk));
            fma8x2(a0, a1, a2, a3, vv, q[k - 8]);
        }
    }
    if (nbmax > 0) {
        int c = (int)p.x;
        float v = __uint_as_float(p.y);
        int rem = deg - it * 16;
        int remmax = max(rem, __shfl_xor_sync(0xffffffffu, rem, 16));

        uint4 q[8];
#pragma unroll
        for (int k = 0; k < 8; ++k) {
            int ck = __shfl_sync(0xffffffffu, c, halfsel | k);
            q[k] = __ldg(&src[ck * 16 + hl]);
        }
#pragma unroll
        for (int k = 0; k < 8; ++k) {
            float vk = __shfl_sync(0xffffffffu, v, halfsel | k);
            ull vv;
            asm("mov.b64 %0,{%1,%1};" : "=l"(vv) : "f"(vk));
            fma8x2(a0, a1, a2, a3, vv, q[k]);
        }
        if (remmax > 8) {
#pragma unroll
            for (int k = 8; k < 16; ++k) {
                int ck = __shfl_sync(0xffffffffu, c, halfsel | k);
                q[k - 8] = __ldg(&src[ck * 16 + hl]);
            }
#pragma unroll
            for (int k = 8; k < 16; ++k) {
                float vk = __shfl_sync(0xffffffffu, v, halfsel | k);
                ull vv;
                asm("mov.b64 %0,{%1,%1};" : "=l"(vv) : "f"(vk));
                fma8x2(a0, a1, a2, a3, vv, q[k - 8]);
            }
        }
    }

    if (valid) {
        float a[8];
        asm("mov.b64 {%0,%1},%2;" : "=f"(a[0]), "=f"(a[1]) : "l"(a0));
        asm("mov.b64 {%0,%1},%2;" : "=f"(a[2]), "=f"(a[3]) : "l"(a1));
        asm("mov.b64 {%0,%1},%2;" : "=f"(a[4]), "=f"(a[5]) : "l"(a2));
        asm("mov.b64 {%0,%1},%2;" : "=f"(a[6]), "=f"(a[7]) : "l"(a3));
        int o = row * 16 + hl;
        if (PHASE == 1) {
            ((uint4*)g_bufA)[o] = pack8(a);
        } else if (PHASE == 2) {
            const float4* at1 = (const float4*)g_attn;
            float4 s10 = at1[hl * 2], s11 = at1[hl * 2 + 1];
            float f[8];
            unpack8(__ldg(&((const uint4*)g_h[0])[o]), f);
            a[0] = fmaf(s10.x, f[0], a[0]); a[1] = fmaf(s10.y, f[1], a[1]);
            a[2] = fmaf(s10.z, f[2], a[2]); a[3] = fmaf(s10.w, f[3], a[3]);
            a[4] = fmaf(s11.x, f[4], a[4]); a[5] = fmaf(s11.y, f[5], a[5]);
            a[6] = fmaf(s11.z, f[6], a[6]); a[7] = fmaf(s11.w, f[7], a[7]);
            ((uint4*)g_bufA)[o] = pack8(a);
        } else {
            const float4* cb4 = (const float4*)g_cb;
            float4 c0 = cb4[hl * 2], c1 = cb4[hl * 2 + 1];
            float4 oa = make_float4(a[0] + c0.x, a[1] + c0.y, a[2] + c0.z, a[3] + c0.w);
            float4 ob = make_float4(a[4] + c1.x, a[5] + c1.y, a[6] + c1.z, a[7] + c1.w);
            ((float4*)out)[row * 32 + hl * 2] = oa;
            ((float4*)out)[row * 32 + hl * 2 + 1] = ob;
        }
    }
}

// ================= K5: dot2 || hop1 (1 dot per 33-block group) ================
// grid = 98*33 = 3234
__global__ __launch_bounds__(256) void k5_kernel() {
    int bx = blockIdx.x;
    int grp = bx / 33, sl = bx % 33;
    if (sl == 0) {
        dot_body(1, grp);
    } else {
        int hb = grp * 32 + (sl - 1);
        if (hb < HOPG) hop_body<1>(hb, nullptr);
    }
}

// ================= K6: dot3 (r2 . bufA) + last-block MLP ======================
__global__ __launch_bounds__(256) void k6_kernel(const float* __restrict__ fc1w,
                                                 const float* __restrict__ fc1b,
                                                 const float* __restrict__ fc2w,
                                                 const float* __restrict__ fc2b,
                                                 const float* __restrict__ B1,
                                                 const float* __restrict__ B2,
                                                 const float* __restrict__ B3) {
    dot_body(2, blockIdx.x);
    __syncthreads();
    __shared__ int is_last;
    int t = threadIdx.x;
    if (t == 0) {
        __threadfence();
        is_last = (atomicAdd(&g_done, 1) == DOTG - 1) ? 1 : 0;
    }
    __syncthreads();
    if (!is_last) return;
    __threadfence();

    __shared__ float m[3 * D];
    __shared__ float t1[3 * D_RED];
    for (int i = t; i < 3 * D; i += 256) {
        int k = i >> 7, d = i & 127;
        const float* Bk = (k == 0) ? B1 : (k == 1) ? B2 : B3;
        m[i] = g_dot[i] * (1.0f / N_NODES) + Bk[d];
    }
    __syncthreads();
    if (t < 3 * D_RED) {
        int k = t / D_RED, r = t % D_RED;
        float s = fc1b[r];
        for (int d = 0; d < D; ++d) s = fmaf(m[k * D + d], fc1w[d * D_RED + r], s);
        t1[t] = s > 0.f ? s : 0.f;
    }
    __syncthreads();
    if (t < D) {
        float lg[3];
#pragma unroll
        for (int k = 0; k < 3; ++k) {
            float s = fc2b[t];
            for (int r = 0; r < D_RED; ++r) s = fmaf(t1[k * D_RED + r], fc2w[r * D + t], s);
            lg[k] = s;
        }
        float mx = fmaxf(lg[0], fmaxf(lg[1], lg[2]));
        float e0 = expf(lg[0] - mx), e1 = expf(lg[1] - mx), e2 = expf(lg[2] - mx);
        float inv = 1.f / (e0 + e1 + e2);
        float a0 = e0 * inv, a1 = e1 * inv, a2 = e2 * inv;
        g_attn[0 * D + t] = a0;
        g_attn[1 * D + t] = a1;
        g_attn[2 * D + t] = a2;
        g_cb[t] = a0 * B1[t] + a1 * B2[t] + a2 * B3[t];
    }
    if (t == 0) g_done = 0;
}

// ================= mix: bufB = a2 (.) h2 + a3 (.) bufA =================
__global__ __launch_bounds__(256) void mix_kernel() {
    int i = blockIdx.x * 256 + threadIdx.x;  // N_NODES*16 uint4 exact
    int hl = i & 15;
    const float4* a2 = (const float4*)(g_attn + 1 * D);
    const float4* a3 = (const float4*)(g_attn + 2 * D);
    float4 s20 = a2[hl * 2], s21 = a2[hl * 2 + 1];
    float4 s30 = a3[hl * 2], s31 = a3[hl * 2 + 1];
    float u[8], h[8];
    unpack8(((const uint4*)g_bufA)[i], u);
    unpack8(((const uint4*)g_h[1])[i], h);
    float r[8];
    r[0] = s20.x * h[0] + s30.x * u[0]; r[1] = s20.y * h[1] + s30.y * u[1];
    r[2] = s20.z * h[2] + s30.z * u[2]; r[3] = s20.w * h[3] + s30.w * u[3];
    r[4] = s21.x * h[4] + s31.x * u[4]; r[5] = s21.y * h[5] + s31.y * u[5];
    r[6] = s21.z * h[6] + s31.z * u[6]; r[7] = s21.w * h[7] + s31.w * u[7];
    ((uint4*)g_bufB)[i] = pack8(r);
}

// ================= hop2 =================
__global__ __launch_bounds__(256) void hop2_kernel() {
    hop_body<2>(blockIdx.x, nullptr);
}

// ================= hop3 + zero tail (state reset for next launch) =============
__global__ __launch_bounds__(256) void hop3_kernel(float* __restrict__ out) {
    int bx = blockIdx.x;
    if (bx < HOPG) {
        hop_body<3>(bx, out);
    } else {
        int z = (bx - HOPG) * 256 + threadIdx.x;
        if (z < N_NODES) {
            g_counts[z] = 0;
            g_r1[z] = 0.f;
            g_r2[z] = 0.f;
        }
        if (z < 3 * D) g_dot[z] = 0.f;
    }
}

// ================= launch =================
extern "C" void kernel_launch(void* const* d_in, const int* in_sizes, int n_in,
                              void* d_out, int out_size) {
    const float* features = (const float*)d_in[0];
    const int*   erow     = (const int*)d_in[1];
    const int*   ecol     = (const int*)d_in[2];
    const float* eval_    = (const float*)d_in[3];
    const float* W1 = (const float*)d_in[4];
    const float* B1 = (const float*)d_in[5];
    const float* W2 = (const float*)d_in[6];
    const float* B2 = (const float*)d_in[7];
    const float* W3 = (const float*)d_in[8];
    const float* B3 = (const float*)d_in[9];
    const float* fc1w = (const float*)d_in[10];
    const float* fc1b = (const float*)d_in[11];
    const float* fc2w = (const float*)d_in[12];
    const float* fc2b = (const float*)d_in[13];
    float* out = (float*)d_out;

    k1_kernel<<<3958, 256>>>(features, W1, W2, W3, erow, ecol, eval_);
    k2_kernel<<<1564, 256>>>();
    scan_kernel<<<783, 256>>>();
    k4_kernel<<<DOTG + EG8, 256>>>(erow, ecol, eval_);
    k5_kernel<<<3234, 256>>>();
    k6_kernel<<<DOTG, 256>>>(fc1w, fc1b, fc2w, fc2b, B1, B2, B3);
    mix_kernel<<<HOPG, 256>>>();
    hop2_kernel<<<HOPG, 256>>>();
    hop3_kernel<<<HOPG + 196, 256>>>(out);
}

// round 14
// speedup vs baseline: 1.2269x; 1.0420x over previous
#include <cuda_runtime.h>
#include <cuda_fp16.h>
#include <mma.h>
#include <math.h>

using namespace nvcuda;

typedef unsigned long long ull;

#define N_NODES 50000
#define N_PAD   50048
#define N_EDGES 800000
#define D 128
#define D_RED 32
#define EG 782          // ceil(200000/256) int4 edge blocks
#define EG8 391         // ceil(100000/256) 8-edge blocks
#define DOTG 98         // ceil(50000/512) dot blocks
#define HOPG 3125       // ceil(50000/16) hop blocks
#define LDMA 136        // skewed smem leading dim (halves)

// ---------------- scratch ----------------
__device__ __half g_x16[N_PAD * D];
__device__ __half g_w16[3][D * D];
__device__ __half g_h[3][N_PAD * D];
__device__ __half g_bufA[N_NODES * D];
__device__ __half g_bufB[N_NODES * D];
__device__ int    g_counts[N_NODES];
__device__ int    g_rowptr[N_NODES + 1];
__device__ int    g_cursor[N_NODES];
__device__ uint2  g_epack[N_EDGES];
__device__ float  g_r1[N_NODES];
__device__ float  g_r2[N_NODES];
__device__ float  g_dot[3 * D];
__device__ float  g_attn[3 * D];
__device__ float  g_cb[D];
__device__ int    g_done;

__device__ __forceinline__ float fast_tanh(float x) {
    float t = __expf(2.0f * x);
    return 1.0f - __fdividef(2.0f, t + 1.0f);
}

// ================= K1: Xcvt || count_r1 || Wcvt =================
// grid = 782*5 + 48 = 3958.  bx<3910: (bx%5==0 -> count, else xcvt); tail: Wcvt.
__global__ __launch_bounds__(256) void k1_kernel(const float* __restrict__ X,
                                                 const float* __restrict__ W1,
                                                 const float* __restrict__ W2,
                                                 const float* __restrict__ W3,
                                                 const int* __restrict__ erow,
                                                 const int* __restrict__ ecol,
                                                 const float* __restrict__ eval_) {
    int bx = blockIdx.x, tid = threadIdx.x;
    if (bx >= 3910) {
        int idx = (bx - 3910) * 256 + tid;   // 12288 float4s
        int k = idx / 4096, o4 = idx % 4096;
        const float4* Wk4 = (const float4*)(k == 0 ? W1 : k == 1 ? W2 : W3);
        float4 w = Wk4[o4];
        __half2 h0 = __floats2half2_rn(w.x, w.y);
        __half2 h1 = __floats2half2_rn(w.z, w.w);
        ((uint2*)g_w16[k])[o4] = make_uint2(*(unsigned*)&h0, *(unsigned*)&h1);
        return;
    }
    int grp = bx / 5, sl = bx % 5;
    if (sl == 0) {
        int i = grp * 256 + tid;
        if (i < N_EDGES / 4) {
            int4 r = ((const int4*)erow)[i];
            int4 c = ((const int4*)ecol)[i];
            float4 v = ((const float4*)eval_)[i];
            atomicAdd(&g_counts[r.x], 1);
            atomicAdd(&g_counts[r.y], 1);
            atomicAdd(&g_counts[r.z], 1);
            atomicAdd(&g_counts[r.w], 1);
            atomicAdd(&g_r1[c.x], v.x);
            atomicAdd(&g_r1[c.y], v.y);
            atomicAdd(&g_r1[c.z], v.z);
            atomicAdd(&g_r1[c.w], v.w);
        }
    } else {
        int i = (grp * 4 + (sl - 1)) * 256 + tid;   // over N_PAD*16 uint4, exact
        int r = i >> 4;
        uint4 o = make_uint4(0, 0, 0, 0);
        if (r < N_NODES) {
            const float4* x4 = (const float4*)X;
            float4 f0 = x4[i * 2], f1 = x4[i * 2 + 1];
            __half2 h0 = __floats2half2_rn(f0.x, f0.y);
            __half2 h1 = __floats2half2_rn(f0.z, f0.w);
            __half2 h2 = __floats2half2_rn(f1.x, f1.y);
            __half2 h3 = __floats2half2_rn(f1.z, f1.w);
            o.x = *(unsigned*)&h0; o.y = *(unsigned*)&h1;
            o.z = *(unsigned*)&h2; o.w = *(unsigned*)&h3;
        }
        ((uint4*)g_x16)[i] = o;
    }
}

// ================= gemm body (skewed smem, B staged in 2 phases) =============
__device__ __forceinline__ void gemm_body(int k, int rb) {
    __shared__ __half As[64 * LDMA];   // 17408 B
    __shared__ __half Bs[64 * LDMA];   // 17408 B
    int tid = threadIdx.x;
    int row0 = rb * 64;
    __half* out = g_h[k];

    {
        const uint4* src = (const uint4*)(g_x16 + row0 * D);
        for (int i = tid; i < 64 * 16; i += 256) {
            int r = i >> 4, c4 = i & 15;
            *(uint4*)(As + r * LDMA + c4 * 8) = src[i];
        }
    }

    int warp = tid >> 5;
    int wr = warp >> 1;
    int wc0 = (warp & 1) * 4;

    wmma::fragment<wmma::accumulator, 16, 16, 16, float> acc[4];
#pragma unroll
    for (int c = 0; c < 4; ++c) wmma::fill_fragment(acc[c], 0.f);

#pragma unroll
    for (int ph = 0; ph < 2; ++ph) {
        __syncthreads();
        {
            const uint4* wsrc = (const uint4*)(g_w16[k] + ph * 64 * D);
            for (int i = tid; i < 64 * 16; i += 256) {
                int r = i >> 4, c4 = i & 15;
                *(uint4*)(Bs + r * LDMA + c4 * 8) = wsrc[i];
            }
        }
        __syncthreads();
#pragma unroll
        for (int k16 = 0; k16 < 4; ++k16) {
            wmma::fragment<wmma::matrix_a, 16, 16, 16, __half, wmma::row_major> a;
            wmma::load_matrix_sync(a, As + wr * 16 * LDMA + (ph * 4 + k16) * 16, LDMA);
#pragma unroll
            for (int c = 0; c < 4; ++c) {
                wmma::fragment<wmma::matrix_b, 16, 16, 16, __half, wmma::row_major> b;
                wmma::load_matrix_sync(b, Bs + k16 * 16 * LDMA + (wc0 + c) * 16, LDMA);
                wmma::mma_sync(acc[c], a, b, acc[c]);
            }
        }
    }
#pragma unroll
    for (int c = 0; c < 4; ++c) {
        wmma::fragment<wmma::accumulator, 16, 16, 16, __half> hacc;
#pragma unroll
        for (int i = 0; i < hacc.num_elements; ++i)
            hacc.x[i] = __float2half(fast_tanh(acc[c].x[i]));
        wmma::store_matrix_sync(out + (row0 + wr * 16) * D + (wc0 + c) * 16, hacc, D,
                                wmma::mem_row_major);
    }
}

// ================= K2: gemm k=0,1 =================
__global__ __launch_bounds__(256) void k2_kernel() {
    gemm_body(blockIdx.x / 782, blockIdx.x % 782);
}

// ================= K3: scan (1 block) || gemm k=2 (782 blocks) =================
__global__ __launch_bounds__(256) void scan_kernel() {
    if (blockIdx.x > 0) {
        gemm_body(2, blockIdx.x - 1);
        return;
    }
    const int P4 = 49;
    const int TOT4 = N_NODES / 4;   // 12500
    int t = threadIdx.x;
    int sum = 0;
    for (int i = 0; i < P4; ++i) {
        int idx4 = t * P4 + i;
        if (idx4 < TOT4) {
            int4 c = ((const int4*)g_counts)[idx4];
            sum += c.x + c.y + c.z + c.w;
        }
    }
    int lane = t & 31, wid = t >> 5;
    int x = sum;
#pragma unroll
    for (int o = 1; o < 32; o <<= 1) {
        int y = __shfl_up_sync(0xffffffffu, x, o);
        if (lane >= o) x += y;
    }
    __shared__ int wsum[8];
    if (lane == 31) wsum[wid] = x;
    __syncthreads();
    if (wid == 0 && lane < 8) {
        int w = wsum[lane];
#pragma unroll
        for (int o = 1; o < 8; o <<= 1) {
            int y = __shfl_up_sync(0xffu, w, o);
            if (lane >= o) w += y;
        }
        wsum[lane] = w;
    }
    __syncthreads();
    int run = x - sum + (wid > 0 ? wsum[wid - 1] : 0);
    for (int i = 0; i < P4; ++i) {
        int idx4 = t * P4 + i;
        if (idx4 < TOT4) {
            int4 c = ((const int4*)g_counts)[idx4];
            int b = idx4 * 4;
            g_rowptr[b] = run;     g_cursor[b] = run;     run += c.x;
            g_rowptr[b + 1] = run; g_cursor[b + 1] = run; run += c.y;
            g_rowptr[b + 2] = run; g_cursor[b + 2] = run; run += c.z;
            g_rowptr[b + 3] = run; g_cursor[b + 3] = run; run += c.w;
        }
    }
    if (t == 0) g_rowptr[N_NODES] = N_EDGES;
}

// ================= dot body =================
// br0: r1 . h1   br1: r2 . h2   br2: r2 . bufA   (m3 = r2^T (A h3) / N)
__device__ __forceinline__ void dot_body(int br, int vb) {
    const float* rk = (br == 0) ? g_r1 : g_r2;
    const __half2* f2 = (br == 0) ? (const __half2*)g_h[0]
                      : (br == 1) ? (const __half2*)g_h[1]
                                  : (const __half2*)g_bufA;
    __shared__ float2 sm[4][64];
    int t = threadIdx.x;
    int d2 = t & 63, grp = t >> 6;
    int r0 = vb * 512 + grp * 128;
    int rend = min(r0 + 128, N_NODES);
    float2 s = make_float2(0.f, 0.f);
    for (int r = r0; r < rend; ++r) {
        float w = __ldg(&rk[r]);
        float2 x = __half22float2(f2[r * 64 + d2]);
        s.x += w * x.x; s.y += w * x.y;
    }
    sm[grp][d2] = s;
    __syncthreads();
    if (t < 64) {
        float2 tot = sm[0][t];
        tot.x += sm[1][t].x + sm[2][t].x + sm[3][t].x;
        tot.y += sm[1][t].y + sm[2][t].y + sm[3][t].y;
        atomicAdd(&g_dot[br * D + t * 2], tot.x);
        atomicAdd(&g_dot[br * D + t * 2 + 1], tot.y);
    }
}

// ================= K4: dot1 || fill_r2 (8 edges/thread) =================
__global__ __launch_bounds__(256) void k4_kernel(const int* __restrict__ erow,
                                                 const int* __restrict__ ecol,
                                                 const float* __restrict__ eval_) {
    int bx = blockIdx.x;
    if (bx < DOTG) {
        dot_body(0, bx);
        return;
    }
    int i = (bx - DOTG) * 256 + threadIdx.x;   // 8-edge packets
    if (i >= N_EDGES / 8) return;
    const int4* er4 = (const int4*)erow;
    const int4* ec4 = (const int4*)ecol;
    const float4* ev4 = (const float4*)eval_;
#pragma unroll
    for (int hh = 0; hh < 2; ++hh) {
        int q = i * 2 + hh;
        int4 r = er4[q];
        int4 c = ec4[q];
        float4 v = ev4[q];
        int p0 = atomicAdd(&g_cursor[r.x], 1);
        int p1 = atomicAdd(&g_cursor[r.y], 1);
        int p2 = atomicAdd(&g_cursor[r.z], 1);
        int p3 = atomicAdd(&g_cursor[r.w], 1);
        g_epack[p0] = make_uint2((unsigned)c.x, __float_as_uint(v.x));
        g_epack[p1] = make_uint2((unsigned)c.y, __float_as_uint(v.y));
        g_epack[p2] = make_uint2((unsigned)c.z, __float_as_uint(v.z));
        g_epack[p3] = make_uint2((unsigned)c.w, __float_as_uint(v.w));
        atomicAdd(&g_r2[c.x], v.x * __ldg(&g_r1[r.x]));
        atomicAdd(&g_r2[c.y], v.y * __ldg(&g_r1[r.y]));
        atomicAdd(&g_r2[c.z], v.z * __ldg(&g_r1[r.z]));
        atomicAdd(&g_r2[c.w], v.w * __ldg(&g_r1[r.w]));
    }
}

// ================= hop helpers =================
__device__ __forceinline__ void fma8x2(ull& a0, ull& a1, ull& a2, ull& a3,
                                       ull vv, uint4 q) {
    float2 f0 = __half22float2(*reinterpret_cast<const __half2*>(&q.x));
    float2 f1 = __half22float2(*reinterpret_cast<const __half2*>(&q.y));
    float2 f2 = __half22float2(*reinterpret_cast<const __half2*>(&q.z));
    float2 f3 = __half22float2(*reinterpret_cast<const __half2*>(&q.w));
    ull b0, b1, b2, b3;
    asm("mov.b64 %0,{%1,%2};" : "=l"(b0) : "f"(f0.x), "f"(f0.y));
    asm("mov.b64 %0,{%1,%2};" : "=l"(b1) : "f"(f1.x), "f"(f1.y));
    asm("mov.b64 %0,{%1,%2};" : "=l"(b2) : "f"(f2.x), "f"(f2.y));
    asm("mov.b64 %0,{%1,%2};" : "=l"(b3) : "f"(f3.x), "f"(f3.y));
    asm("fma.rn.f32x2 %0,%1,%2,%0;" : "+l"(a0) : "l"(vv), "l"(b0));
    asm("fma.rn.f32x2 %0,%1,%2,%0;" : "+l"(a1) : "l"(vv), "l"(b1));
    asm("fma.rn.f32x2 %0,%1,%2,%0;" : "+l"(a2) : "l"(vv), "l"(b2));
    asm("fma.rn.f32x2 %0,%1,%2,%0;" : "+l"(a3) : "l"(vv), "l"(b3));
}

__device__ __forceinline__ void hfma8(__half2& h0, __half2& h1, __half2& h2, __half2& h3,
                                      __half2 hv, uint4 q) {
    h0 = __hfma2(hv, *reinterpret_cast<const __half2*>(&q.x), h0);
    h1 = __hfma2(hv, *reinterpret_cast<const __half2*>(&q.y), h1);
    h2 = __hfma2(hv, *reinterpret_cast<const __half2*>(&q.z), h2);
    h3 = __hfma2(hv, *reinterpret_cast<const __half2*>(&q.w), h3);
}

__device__ __forceinline__ void unpack8(uint4 q, float* f) {
    float2 x;
    x = __half22float2(*(__half2*)&q.x); f[0] = x.x; f[1] = x.y;
    x = __half22float2(*(__half2*)&q.y); f[2] = x.x; f[3] = x.y;
    x = __half22float2(*(__half2*)&q.z); f[4] = x.x; f[5] = x.y;
    x = __half22float2(*(__half2*)&q.w); f[6] = x.x; f[7] = x.y;
}

__device__ __forceinline__ uint4 pack8(const float* a) {
    __half2 h0 = __floats2half2_rn(a[0], a[1]);
    __half2 h1 = __floats2half2_rn(a[2], a[3]);
    __half2 h2 = __floats2half2_rn(a[4], a[5]);
    __half2 h3 = __floats2half2_rn(a[6], a[7]);
    uint4 r;
    r.x = *(unsigned*)&h0; r.y = *(unsigned*)&h1;
    r.z = *(unsigned*)&h2; r.w = *(unsigned*)&h3;
    return r;
}

// ================= hop body: peeled loop; fp16 accum for PHASE 1-2 =============
// PHASE 1: bufA = A h3                 (fp16 accumulate, output fp16 anyway)
// PHASE 2: bufA = A bufB + a1 (.) h1   (fp16 accumulate, output fp16 anyway)
// PHASE 3: out  = A bufA + cb          (f32x2 accumulate, fp32 output)
template <int PHASE>
__device__ __forceinline__ void hop_body(int blk, float* __restrict__ out) {
    const uint4* src = (PHASE == 1) ? (const uint4*)g_h[2]
                     : (PHASE == 2) ? (const uint4*)g_bufB
                                    : (const uint4*)g_bufA;
    constexpr bool H16 = (PHASE <= 2);

    int lane = threadIdx.x & 31;
    int warp = threadIdx.x >> 5;
    int hl = lane & 15;
    int halfsel = lane & 16;
    int row = blk * 16 + warp * 2 + (lane >> 4);
    bool valid = row < N_NODES;
    int s = valid ? g_rowptr[row] : 0;
    int e = valid ? g_rowptr[row + 1] : 0;
    int deg = e - s;
    int nb = (deg + 15) >> 4;
    int nbmax = max(nb, __shfl_xor_sync(0xffffffffu, nb, 16));

    ull a0 = 0, a1 = 0, a2 = 0, a3 = 0;
    __half2 zh = __float2half2_rn(0.f);
    __half2 h0 = zh, h1 = zh, h2 = zh, h3 = zh;

    int idx0 = s + hl;
    uint2 p = (idx0 < e) ? __ldg(&g_epack[idx0]) : make_uint2(0, 0);

    int it = 0;
    for (; it + 1 < nbmax; ++it) {
        int c = (int)p.x;
        float v = __uint_as_float(p.y);
        int nidx = s + (it + 1) * 16 + hl;
        p = (nidx < e) ? __ldg(&g_epack[nidx]) : make_uint2(0, 0);

        uint4 q[8];
#pragma unroll
        for (int k = 0; k < 8; ++k) {
            int ck = __shfl_sync(0xffffffffu, c, halfsel | k);
            q[k] = __ldg(&src[ck * 16 + hl]);
        }
#pragma unroll
        for (int k = 0; k < 8; ++k) {
            float vk = __shfl_sync(0xffffffffu, v, halfsel | k);
            if (H16) {
                __half2 hv = __float2half2_rn(vk);
                hfma8(h0, h1, h2, h3, hv, q[k]);
            } else {
                ull vv;
                asm("mov.b64 %0,{%1,%1};" : "=l"(vv) : "f"(vk));
                fma8x2(a0, a1, a2, a3, vv, q[k]);
            }
        }
#pragma unroll
        for (int k = 8; k < 16; ++k) {
            int ck = __shfl_sync(0xffffffffu, c, halfsel | k);
            q[k - 8] = __ldg(&src[ck * 16 + hl]);
        }
#pragma unroll
        for (int k = 8; k < 16; ++k) {
            float vk = __shfl_sync(0xffffffffu, v, halfsel | k);
            if (H16) {
                __half2 hv = __float2half2_rn(vk);
                hfma8(h0, h1, h2, h3, hv, q[k - 8]);
            } else {
                ull vv;
                asm("mov.b64 %0,{%1,%1};" : "=l"(vv) : "f"(vk));
                fma8x2(a0, a1, a2, a3, vv, q[k - 8]);
            }
        }
    }
    if (nbmax > 0) {
        int c = (int)p.x;
        float v = __uint_as_float(p.y);
        int rem = deg - it * 16;
        int remmax = max(rem, __shfl_xor_sync(0xffffffffu, rem, 16));

        uint4 q[8];
#pragma unroll
        for (int k = 0; k < 8; ++k) {
            int ck = __shfl_sync(0xffffffffu, c, halfsel | k);
            q[k] = __ldg(&src[ck * 16 + hl]);
        }
#pragma unroll
        for (int k = 0; k < 8; ++k) {
            float vk = __shfl_sync(0xffffffffu, v, halfsel | k);
            if (H16) {
                __half2 hv = __float2half2_rn(vk);
                hfma8(h0, h1, h2, h3, hv, q[k]);
            } else {
                ull vv;
                asm("mov.b64 %0,{%1,%1};" : "=l"(vv) : "f"(vk));
                fma8x2(a0, a1, a2, a3, vv, q[k]);
            }
        }
        if (remmax > 8) {
#pragma unroll
            for (int k = 8; k < 16; ++k) {
                int ck = __shfl_sync(0xffffffffu, c, halfsel | k);
                q[k - 8] = __ldg(&src[ck * 16 + hl]);
            }
#pragma unroll
            for (int k = 8; k < 16; ++k) {
                float vk = __shfl_sync(0xffffffffu, v, halfsel | k);
                if (H16) {
                    __half2 hv = __float2half2_rn(vk);
                    hfma8(h0, h1, h2, h3, hv, q[k - 8]);
                } else {
                    ull vv;
                    asm("mov.b64 %0,{%1,%1};" : "=l"(vv) : "f"(vk));
                    fma8x2(a0, a1, a2, a3, vv, q[k - 8]);
                }
            }
        }
    }

    if (valid) {
        int o = row * 16 + hl;
        if (PHASE == 1) {
            uint4 r;
            r.x = *(unsigned*)&h0; r.y = *(unsigned*)&h1;
            r.z = *(unsigned*)&h2; r.w = *(unsigned*)&h3;
            ((uint4*)g_bufA)[o] = r;
        } else if (PHASE == 2) {
            float a[8];
            float2 x;
            x = __half22float2(h0); a[0] = x.x; a[1] = x.y;
            x = __half22float2(h1); a[2] = x.x; a[3] = x.y;
            x = __half22float2(h2); a[4] = x.x; a[5] = x.y;
            x = __half22float2(h3); a[6] = x.x; a[7] = x.y;
            const float4* at1 = (const float4*)g_attn;
            float4 s10 = at1[hl * 2], s11 = at1[hl * 2 + 1];
            float f[8];
            unpack8(__ldg(&((const uint4*)g_h[0])[o]), f);
            a[0] = fmaf(s10.x, f[0], a[0]); a[1] = fmaf(s10.y, f[1], a[1]);
            a[2] = fmaf(s10.z, f[2], a[2]); a[3] = fmaf(s10.w, f[3], a[3]);
            a[4] = fmaf(s11.x, f[4], a[4]); a[5] = fmaf(s11.y, f[5], a[5]);
            a[6] = fmaf(s11.z, f[6], a[6]); a[7] = fmaf(s11.w, f[7], a[7]);
            ((uint4*)g_bufA)[o] = pack8(a);
        } else {
            float a[8];
            asm("mov.b64 {%0,%1},%2;" : "=f"(a[0]), "=f"(a[1]) : "l"(a0));
            asm("mov.b64 {%0,%1},%2;" : "=f"(a[2]), "=f"(a[3]) : "l"(a1));
            asm("mov.b64 {%0,%1},%2;" : "=f"(a[4]), "=f"(a[5]) : "l"(a2));
            asm("mov.b64 {%0,%1},%2;" : "=f"(a[6]), "=f"(a[7]) : "l"(a3));
            const float4* cb4 = (const float4*)g_cb;
            float4 c0 = cb4[hl * 2], c1 = cb4[hl * 2 + 1];
            float4 oa = make_float4(a[0] + c0.x, a[1] + c0.y, a[2] + c0.z, a[3] + c0.w);
            float4 ob = make_float4(a[4] + c1.x, a[5] + c1.y, a[6] + c1.z, a[7] + c1.w);
            ((float4*)out)[row * 32 + hl * 2] = oa;
            ((float4*)out)[row * 32 + hl * 2 + 1] = ob;
        }
    }
}

// ================= K5: dot2 || hop1 (1 dot per 33-block group) ================
// grid = 98*33 = 3234
__global__ __launch_bounds__(256) void k5_kernel() {
    int bx = blockIdx.x;
    int grp = bx / 33, sl = bx % 33;
    if (sl == 0) {
        dot_body(1, grp);
    } else {
        int hb = grp * 32 + (sl - 1);
        if (hb < HOPG) hop_body<1>(hb, nullptr);
    }
}

// ================= K6: dot3 (r2 . bufA) + last-block MLP ======================
__global__ __launch_bounds__(256) void k6_kernel(const float* __restrict__ fc1w,
                                                 const float* __restrict__ fc1b,
                                                 const float* __restrict__ fc2w,
                                                 const float* __restrict__ fc2b,
                                                 const float* __restrict__ B1,
                                                 const float* __restrict__ B2,
                                                 const float* __restrict__ B3) {
    dot_body(2, blockIdx.x);
    __syncthreads();
    __shared__ int is_last;
    int t = threadIdx.x;
    if (t == 0) {
        __threadfence();
        is_last = (atomicAdd(&g_done, 1) == DOTG - 1) ? 1 : 0;
    }
    __syncthreads();
    if (!is_last) return;
    __threadfence();

    __shared__ float m[3 * D];
    __shared__ float t1[3 * D_RED];
    for (int i = t; i < 3 * D; i += 256) {
        int k = i >> 7, d = i & 127;
        const float* Bk = (k == 0) ? B1 : (k == 1) ? B2 : B3;
        m[i] = g_dot[i] * (1.0f / N_NODES) + Bk[d];
    }
    __syncthreads();
    if (t < 3 * D_RED) {
        int k = t / D_RED, r = t % D_RED;
        float s = fc1b[r];
        for (int d = 0; d < D; ++d) s = fmaf(m[k * D + d], fc1w[d * D_RED + r], s);
        t1[t] = s > 0.f ? s : 0.f;
    }
    __syncthreads();
    if (t < D) {
        float lg[3];
#pragma unroll
        for (int k = 0; k < 3; ++k) {
            float s = fc2b[t];
            for (int r = 0; r < D_RED; ++r) s = fmaf(t1[k * D_RED + r], fc2w[r * D + t], s);
            lg[k] = s;
        }
        float mx = fmaxf(lg[0], fmaxf(lg[1], lg[2]));
        float e0 = expf(lg[0] - mx), e1 = expf(lg[1] - mx), e2 = expf(lg[2] - mx);
        float inv = 1.f / (e0 + e1 + e2);
        float a0 = e0 * inv, a1 = e1 * inv, a2 = e2 * inv;
        g_attn[0 * D + t] = a0;
        g_attn[1 * D + t] = a1;
        g_attn[2 * D + t] = a2;
        g_cb[t] = a0 * B1[t] + a1 * B2[t] + a2 * B3[t];
    }
    if (t == 0) g_done = 0;
}

// ================= mix: bufB = a2 (.) h2 + a3 (.) bufA =================
__global__ __launch_bounds__(256) void mix_kernel() {
    int i = blockIdx.x * 256 + threadIdx.x;  // N_NODES*16 uint4 exact
    int hl = i & 15;
    const float4* a2 = (const float4*)(g_attn + 1 * D);
    const float4* a3 = (const float4*)(g_attn + 2 * D);
    float4 s20 = a2[hl * 2], s21 = a2[hl * 2 + 1];
    float4 s30 = a3[hl * 2], s31 = a3[hl * 2 + 1];
    float u[8], h[8];
    unpack8(((const uint4*)g_bufA)[i], u);
    unpack8(((const uint4*)g_h[1])[i], h);
    float r[8];
    r[0] = s20.x * h[0] + s30.x * u[0]; r[1] = s20.y * h[1] + s30.y * u[1];
    r[2] = s20.z * h[2] + s30.z * u[2]; r[3] = s20.w * h[3] + s30.w * u[3];
    r[4] = s21.x * h[4] + s31.x * u[4]; r[5] = s21.y * h[5] + s31.y * u[5];
    r[6] = s21.z * h[6] + s31.z * u[6]; r[7] = s21.w * h[7] + s31.w * u[7];
    ((uint4*)g_bufB)[i] = pack8(r);
}

// ================= hop2 =================
__global__ __launch_bounds__(256) void hop2_kernel() {
    hop_body<2>(blockIdx.x, nullptr);
}

// ================= hop3 + zero tail (state reset for next launch) =============
__global__ __launch_bounds__(256) void hop3_kernel(float* __restrict__ out) {
    int bx = blockIdx.x;
    if (bx < HOPG) {
        hop_body<3>(bx, out);
    } else {
        int z = (bx - HOPG) * 256 + threadIdx.x;
        if (z < N_NODES) {
            g_counts[z] = 0;
            g_r1[z] = 0.f;
            g_r2[z] = 0.f;
        }
        if (z < 3 * D) g_dot[z] = 0.f;
    }
}

// ================= launch =================
extern "C" void kernel_launch(void* const* d_in, const int* in_sizes, int n_in,
                              void* d_out, int out_size) {
    const float* features = (const float*)d_in[0];
    const int*   erow     = (const int*)d_in[1];
    const int*   ecol     = (const int*)d_in[2];
    const float* eval_    = (const float*)d_in[3];
    const float* W1 = (const float*)d_in[4];
    const float* B1 = (const float*)d_in[5];
    const float* W2 = (const float*)d_in[6];
    const float* B2 = (const float*)d_in[7];
    const float* W3 = (const float*)d_in[8];
    const float* B3 = (const float*)d_in[9];
    const float* fc1w = (const float*)d_in[10];
    const float* fc1b = (const float*)d_in[11];
    const float* fc2w = (const float*)d_in[12];
    const float* fc2b = (const float*)d_in[13];
    float* out = (float*)d_out;

    k1_kernel<<<3958, 256>>>(features, W1, W2, W3, erow, ecol, eval_);
    k2_kernel<<<1564, 256>>>();
    scan_kernel<<<783, 256>>>();
    k4_kernel<<<DOTG + EG8, 256>>>(erow, ecol, eval_);
    k5_kernel<<<3234, 256>>>();
    k6_kernel<<<DOTG, 256>>>(fc1w, fc1b, fc2w, fc2b, B1, B2, B3);
    mix_kernel<<<HOPG, 256>>>();
    hop2_kernel<<<HOPG, 256>>>();
    hop3_kernel<<<HOPG + 196, 256>>>(out);
}